// round 10
// baseline (speedup 1.0000x reference)
#include <cuda_runtime.h>
#include <math.h>

// SimpleLSTM: B=4096, T_HIST=60, D_IN=2, H=128, L=2, T_OUT=360
// Persistent kernel, MROWS=16 batch rows per block, grid=256.
// Weights pre-transposed to k-major (coalesced lane access), activations
// stored k-major as batch-row pairs, compute via packed fma.rn.f32x2.

#define MROWS   16
#define NPAIR   8          // MROWS/2
#define HDIM    128
#define NTHREAD 128
#define T_HIST  60
#define T_OUT   360
#define XSTRIDE 9          // padded row stride (float2) for k-major activations

typedef unsigned long long ull;

// Transposed weights: 8 mats (encWih0,encWih1,encWhh0,encWhh1,decWih0,decWih1,
// decWhh0,decWhh1), each [64 k-pairs][512 rows] float2 = {W[row][2k2],W[row][2k2+1]}
__device__ float2 g_W2[8][64 * 512];

__device__ __forceinline__ ull ffma2(ull a, ull b, ull c) {
    ull d;
    asm("fma.rn.f32x2 %0, %1, %2, %3;" : "=l"(d) : "l"(a), "l"(b), "l"(c));
    return d;
}
__device__ __forceinline__ ull dup2(float w) {
    ull d;
    asm("mov.b64 %0, {%1, %1};" : "=l"(d) : "f"(w));
    return d;
}
__device__ __forceinline__ ull pack2(float a, float b) {
    ull d;
    asm("mov.b64 %0, {%1, %2};" : "=l"(d) : "f"(a), "f"(b));
    return d;
}
__device__ __forceinline__ void unpack2(ull v, float& a, float& b) {
    asm("mov.b64 {%0, %1}, %2;" : "=f"(a), "=f"(b) : "l"(v));
}

__device__ __forceinline__ float sigf(float x) {
    return 1.0f / (1.0f + expf(-x));
}

// ---------------- weight transpose kernel ----------------
__global__ void transpose_weights(
    const float* __restrict__ eWih, const float* __restrict__ eWhh,
    const float* __restrict__ dWih, const float* __restrict__ dWhh)
{
    int idx = blockIdx.x * 256 + threadIdx.x;   // 0 .. 8*32768-1
    int mat = idx >> 15;
    int rem = idx & 32767;
    int k2  = rem >> 9;
    int row = rem & 511;
    int grp = mat >> 1;
    int lay = mat & 1;
    const float* src =
        (grp == 0 ? eWih : grp == 1 ? eWhh : grp == 2 ? dWih : dWhh) + lay * 65536;
    float a = src[row * 128 + 2 * k2];
    float b = src[row * 128 + 2 * k2 + 1];
    g_W2[mat][k2 * 512 + row] = make_float2(a, b);
}

// ---------------- gate GEMM on batch-row pairs ----------------
// acc[p][j] (f32x2, pair p = batch rows 2p,2p+1; j = gate i/f/g/o) +=
//   sum_k x[pair][k] * W[tid+128j][k]
__device__ __forceinline__ void gemm_pairs(
    ull (&acc)[NPAIR][4],
    const float2* __restrict__ xb,      // shared, k-major [128][XSTRIDE]
    const float2* __restrict__ W2,      // global, [64][512]
    int tid)
{
#pragma unroll 2
    for (int k2 = 0; k2 < 64; ++k2) {
        float2 w0 = W2[k2 * 512 + tid];
        float2 w1 = W2[k2 * 512 + tid + 128];
        float2 w2 = W2[k2 * 512 + tid + 256];
        float2 w3 = W2[k2 * 512 + tid + 384];

        const ull* x0 = (const ull*)(xb + (2 * k2)     * XSTRIDE);
        const ull* x1 = (const ull*)(xb + (2 * k2 + 1) * XSTRIDE);
        ull xa[NPAIR], xc[NPAIR];
#pragma unroll
        for (int p = 0; p < NPAIR; ++p) { xa[p] = x0[p]; xc[p] = x1[p]; }

        ull w0x = dup2(w0.x), w0y = dup2(w0.y);
        ull w1x = dup2(w1.x), w1y = dup2(w1.y);
        ull w2x = dup2(w2.x), w2y = dup2(w2.y);
        ull w3x = dup2(w3.x), w3y = dup2(w3.y);

#pragma unroll
        for (int p = 0; p < NPAIR; ++p) {
            acc[p][0] = ffma2(w0x, xa[p], acc[p][0]);
            acc[p][1] = ffma2(w1x, xa[p], acc[p][1]);
            acc[p][2] = ffma2(w2x, xa[p], acc[p][2]);
            acc[p][3] = ffma2(w3x, xa[p], acc[p][3]);
            acc[p][0] = ffma2(w0y, xc[p], acc[p][0]);
            acc[p][1] = ffma2(w1y, xc[p], acc[p][1]);
            acc[p][2] = ffma2(w2y, xc[p], acc[p][2]);
            acc[p][3] = ffma2(w3y, xc[p], acc[p][3]);
        }
    }
}

// One LSTM layer step. xb: input activations (k-major pairs), hio: this layer's
// h state (k-major pairs, updated in place), cst: c state (scalar regs).
__device__ __forceinline__ void lstm_layer(
    const float2* __restrict__ xb,
    float2* __restrict__ hio,
    float (&cst)[MROWS],
    const float2* __restrict__ Wih2,
    const float2* __restrict__ Whh2,
    const ull (&bias)[4],
    int tid)
{
    ull acc[NPAIR][4];
#pragma unroll
    for (int p = 0; p < NPAIR; ++p)
#pragma unroll
        for (int j = 0; j < 4; ++j) acc[p][j] = bias[j];

    gemm_pairs(acc, xb,  Wih2, tid);
    gemm_pairs(acc, hio, Whh2, tid);

    __syncthreads();   // all reads of xb/hio done before hio overwrite

#pragma unroll
    for (int p = 0; p < NPAIR; ++p) {
        float i0, i1, f0, f1, g0, g1, o0, o1;
        unpack2(acc[p][0], i0, i1);
        unpack2(acc[p][1], f0, f1);
        unpack2(acc[p][2], g0, g1);
        unpack2(acc[p][3], o0, o1);
        float c0 = sigf(f0) * cst[2 * p]     + sigf(i0) * tanhf(g0);
        float c1 = sigf(f1) * cst[2 * p + 1] + sigf(i1) * tanhf(g1);
        cst[2 * p]     = c0;
        cst[2 * p + 1] = c1;
        float h0 = sigf(o0) * tanhf(c0);
        float h1 = sigf(o1) * tanhf(c1);
        *(ull*)(hio + tid * XSTRIDE + p) = pack2(h0, h1);
    }
    __syncthreads();   // new h visible to all
}

__global__ __launch_bounds__(NTHREAD, 2)
void lstm_persistent_kernel(
    const float* __restrict__ history,   // (B, 60, 2)
    const float* __restrict__ emb_W,     // (128, 2)
    const float* __restrict__ emb_b,     // (128)
    const float* __restrict__ enc_bih,   // (2, 512)
    const float* __restrict__ enc_bhh,
    const float* __restrict__ dec_bih,
    const float* __restrict__ dec_bhh,
    const float* __restrict__ out_W,     // (2, 128)
    const float* __restrict__ out_b,     // (2)
    float* __restrict__ out)             // (B, 360, 2)
{
    __shared__ float2 xp [HDIM * XSTRIDE];
    __shared__ float2 hp0[HDIM * XSTRIDE];
    __shared__ float2 hp1[HDIM * XSTRIDE];
    __shared__ float  pred_sh[MROWS][2];
    __shared__ float  outw_sh[2][HDIM];
    __shared__ float  outb_sh[2];

    const int tid = threadIdx.x;
    const int b0  = blockIdx.x * MROWS;

    const float ew0 = emb_W[tid * 2 + 0];
    const float ew1 = emb_W[tid * 2 + 1];
    const float eb  = emb_b[tid];

    ull be0[4], be1[4], bd0[4], bd1[4];
#pragma unroll
    for (int j = 0; j < 4; ++j) {
        int g = tid + 128 * j;
        float v;
        v = enc_bih[g]       + enc_bhh[g];        be0[j] = dup2(v);
        v = enc_bih[512 + g] + enc_bhh[512 + g];  be1[j] = dup2(v);
        v = dec_bih[g]       + dec_bhh[g];        bd0[j] = dup2(v);
        v = dec_bih[512 + g] + dec_bhh[512 + g];  bd1[j] = dup2(v);
    }

    outw_sh[0][tid] = out_W[tid];
    outw_sh[1][tid] = out_W[128 + tid];
    if (tid < 2) outb_sh[tid] = out_b[tid];

    float cst0[MROWS], cst1[MROWS];
#pragma unroll
    for (int m = 0; m < MROWS; ++m) { cst0[m] = 0.0f; cst1[m] = 0.0f; }
#pragma unroll
    for (int p = 0; p < NPAIR; ++p) {
        hp0[tid * XSTRIDE + p] = make_float2(0.0f, 0.0f);
        hp1[tid * XSTRIDE + p] = make_float2(0.0f, 0.0f);
    }
    __syncthreads();

    const float2* eW0 = g_W2[0];
    const float2* eW1 = g_W2[1];
    const float2* eU0 = g_W2[2];
    const float2* eU1 = g_W2[3];
    const float2* dW0 = g_W2[4];
    const float2* dW1 = g_W2[5];
    const float2* dU0 = g_W2[6];
    const float2* dU1 = g_W2[7];

    // ---------------- Encoder: 60 steps ----------------
    for (int t = 0; t < T_HIST; ++t) {
#pragma unroll
        for (int p = 0; p < NPAIR; ++p) {
            const float* h0p = history + (size_t)(b0 + 2 * p)     * (T_HIST * 2) + t * 2;
            const float* h1p = history + (size_t)(b0 + 2 * p + 1) * (T_HIST * 2) + t * 2;
            float v0 = h0p[0] * ew0 + h0p[1] * ew1 + eb;
            float v1 = h1p[0] * ew0 + h1p[1] * ew1 + eb;
            *(ull*)(xp + tid * XSTRIDE + p) = pack2(v0, v1);
        }
        __syncthreads();

        lstm_layer(xp,  hp0, cst0, eW0, eU0, be0, tid);
        lstm_layer(hp0, hp1, cst1, eW1, eU1, be1, tid);
    }

    // ---------------- Decoder: 360 autoregressive steps ----------------
    const int wrp  = tid >> 5;
    const int lane = tid & 31;

    for (int t = 0; t < T_OUT; ++t) {
        if (t == 0) {
#pragma unroll
            for (int p = 0; p < NPAIR; ++p)
                xp[tid * XSTRIDE + p] = make_float2(0.0f, 0.0f);
        } else {
#pragma unroll
            for (int p = 0; p < NPAIR; ++p) {
                float v0 = pred_sh[2 * p][0]     * ew0 + pred_sh[2 * p][1]     * ew1 + eb;
                float v1 = pred_sh[2 * p + 1][0] * ew0 + pred_sh[2 * p + 1][1] * ew1 + eb;
                *(ull*)(xp + tid * XSTRIDE + p) = pack2(v0, v1);
            }
        }
        __syncthreads();

        lstm_layer(xp,  hp0, cst0, dW0, dU0, bd0, tid);
        lstm_layer(hp0, hp1, cst1, dW1, dU1, bd1, tid);

        // pred = h1 @ out_W.T + out_b ; 4 warps x 2 pairs each
#pragma unroll
        for (int pp = 0; pp < 2; ++pp) {
            int p = wrp + 4 * pp;
            float a00 = 0.0f, a01 = 0.0f, a10 = 0.0f, a11 = 0.0f;
#pragma unroll
            for (int j = 0; j < 4; ++j) {
                int k = lane + 32 * j;
                float2 hv = hp1[k * XSTRIDE + p];
                float w0 = outw_sh[0][k];
                float w1 = outw_sh[1][k];
                a00 += hv.x * w0;  a01 += hv.x * w1;
                a10 += hv.y * w0;  a11 += hv.y * w1;
            }
#pragma unroll
            for (int off = 16; off > 0; off >>= 1) {
                a00 += __shfl_xor_sync(0xffffffffu, a00, off);
                a01 += __shfl_xor_sync(0xffffffffu, a01, off);
                a10 += __shfl_xor_sync(0xffffffffu, a10, off);
                a11 += __shfl_xor_sync(0xffffffffu, a11, off);
            }
            if (lane == 0) {
                float p00 = a00 + outb_sh[0];
                float p01 = a01 + outb_sh[1];
                float p10 = a10 + outb_sh[0];
                float p11 = a11 + outb_sh[1];
                int m0 = 2 * p, m1 = 2 * p + 1;
                pred_sh[m0][0] = p00;  pred_sh[m0][1] = p01;
                pred_sh[m1][0] = p10;  pred_sh[m1][1] = p11;
                size_t o0 = (size_t)(b0 + m0) * (T_OUT * 2) + (size_t)t * 2;
                size_t o1 = (size_t)(b0 + m1) * (T_OUT * 2) + (size_t)t * 2;
                out[o0] = p00;  out[o0 + 1] = p01;
                out[o1] = p10;  out[o1 + 1] = p11;
            }
        }
        __syncthreads();   // pred_sh stable for next step
    }
}

extern "C" void kernel_launch(void* const* d_in, const int* in_sizes, int n_in,
                              void* d_out, int out_size)
{
    const float* history = (const float*)d_in[0];
    const float* emb_W   = (const float*)d_in[1];
    const float* emb_b   = (const float*)d_in[2];
    const float* enc_Wih = (const float*)d_in[3];
    const float* enc_Whh = (const float*)d_in[4];
    const float* enc_bih = (const float*)d_in[5];
    const float* enc_bhh = (const float*)d_in[6];
    const float* dec_Wih = (const float*)d_in[7];
    const float* dec_Whh = (const float*)d_in[8];
    const float* dec_bih = (const float*)d_in[9];
    const float* dec_bhh = (const float*)d_in[10];
    const float* out_W   = (const float*)d_in[11];
    const float* out_b   = (const float*)d_in[12];
    float* out = (float*)d_out;

    transpose_weights<<<1024, 256>>>(enc_Wih, enc_Whh, dec_Wih, dec_Whh);

    const int B = 4096;
    lstm_persistent_kernel<<<B / MROWS, NTHREAD>>>(
        history, emb_W, emb_b,
        enc_bih, enc_bhh, dec_bih, dec_bhh,
        out_W, out_b, out);
}

// round 11
// speedup vs baseline: 1.0721x; 1.0721x over previous
#include <cuda_runtime.h>
#include <math.h>

// SimpleLSTM: B=4096, T_HIST=60, D_IN=2, H=128, L=2, T_OUT=360
// Persistent kernel, MROWS=16 batch rows per block, grid=256.
// Weights pre-transposed to k-major (coalesced lane access), activations
// stored k-major as batch-row pairs, compute via packed fma.rn.f32x2.

#define MROWS   16
#define NPAIR   8          // MROWS/2
#define HDIM    128
#define NTHREAD 128
#define T_HIST  60
#define T_OUT   360
#define XSTRIDE 9          // padded row stride (float2) for k-major activations

typedef unsigned long long ull;

// Transposed weights: 8 mats (encWih0,encWih1,encWhh0,encWhh1,decWih0,decWih1,
// decWhh0,decWhh1), each [64 k-pairs][512 rows] float2 = {W[row][2k2],W[row][2k2+1]}
__device__ float2 g_W2[8][64 * 512];

__device__ __forceinline__ ull ffma2(ull a, ull b, ull c) {
    ull d;
    asm("fma.rn.f32x2 %0, %1, %2, %3;" : "=l"(d) : "l"(a), "l"(b), "l"(c));
    return d;
}
__device__ __forceinline__ ull dup2(float w) {
    ull d;
    asm("mov.b64 %0, {%1, %1};" : "=l"(d) : "f"(w));
    return d;
}
__device__ __forceinline__ ull pack2(float a, float b) {
    ull d;
    asm("mov.b64 %0, {%1, %2};" : "=l"(d) : "f"(a), "f"(b));
    return d;
}
__device__ __forceinline__ void unpack2(ull v, float& a, float& b) {
    asm("mov.b64 {%0, %1}, %2;" : "=f"(a), "=f"(b) : "l"(v));
}

__device__ __forceinline__ float sigf(float x) {
    return 1.0f / (1.0f + expf(-x));
}

// ---------------- weight transpose kernel ----------------
__global__ void transpose_weights(
    const float* __restrict__ eWih, const float* __restrict__ eWhh,
    const float* __restrict__ dWih, const float* __restrict__ dWhh)
{
    int idx = blockIdx.x * 256 + threadIdx.x;   // 0 .. 8*32768-1
    int mat = idx >> 15;
    int rem = idx & 32767;
    int k2  = rem >> 9;
    int row = rem & 511;
    int grp = mat >> 1;
    int lay = mat & 1;
    const float* src =
        (grp == 0 ? eWih : grp == 1 ? eWhh : grp == 2 ? dWih : dWhh) + lay * 65536;
    float a = src[row * 128 + 2 * k2];
    float b = src[row * 128 + 2 * k2 + 1];
    g_W2[mat][k2 * 512 + row] = make_float2(a, b);
}

// ---------------- gate GEMM on batch-row pairs ----------------
// acc[p][j] (f32x2, pair p = batch rows 2p,2p+1; j = gate i/f/g/o) +=
//   sum_k x[pair][k] * W[tid+128j][k]
__device__ __forceinline__ void gemm_pairs(
    ull (&acc)[NPAIR][4],
    const float2* __restrict__ xb,      // shared, k-major [128][XSTRIDE]
    const float2* __restrict__ W2,      // global, [64][512]
    int tid)
{
#pragma unroll 2
    for (int k2 = 0; k2 < 64; ++k2) {
        float2 w0 = W2[k2 * 512 + tid];
        float2 w1 = W2[k2 * 512 + tid + 128];
        float2 w2 = W2[k2 * 512 + tid + 256];
        float2 w3 = W2[k2 * 512 + tid + 384];

        const ull* x0 = (const ull*)(xb + (2 * k2)     * XSTRIDE);
        const ull* x1 = (const ull*)(xb + (2 * k2 + 1) * XSTRIDE);
        ull xa[NPAIR], xc[NPAIR];
#pragma unroll
        for (int p = 0; p < NPAIR; ++p) { xa[p] = x0[p]; xc[p] = x1[p]; }

        ull w0x = dup2(w0.x), w0y = dup2(w0.y);
        ull w1x = dup2(w1.x), w1y = dup2(w1.y);
        ull w2x = dup2(w2.x), w2y = dup2(w2.y);
        ull w3x = dup2(w3.x), w3y = dup2(w3.y);

#pragma unroll
        for (int p = 0; p < NPAIR; ++p) {
            acc[p][0] = ffma2(w0x, xa[p], acc[p][0]);
            acc[p][1] = ffma2(w1x, xa[p], acc[p][1]);
            acc[p][2] = ffma2(w2x, xa[p], acc[p][2]);
            acc[p][3] = ffma2(w3x, xa[p], acc[p][3]);
            acc[p][0] = ffma2(w0y, xc[p], acc[p][0]);
            acc[p][1] = ffma2(w1y, xc[p], acc[p][1]);
            acc[p][2] = ffma2(w2y, xc[p], acc[p][2]);
            acc[p][3] = ffma2(w3y, xc[p], acc[p][3]);
        }
    }
}

// One LSTM layer step. xb: input activations (k-major pairs), hio: this layer's
// h state (k-major pairs, updated in place), cst: c state (scalar regs).
__device__ __forceinline__ void lstm_layer(
    const float2* __restrict__ xb,
    float2* __restrict__ hio,
    float (&cst)[MROWS],
    const float2* __restrict__ Wih2,
    const float2* __restrict__ Whh2,
    const ull (&bias)[4],
    int tid)
{
    ull acc[NPAIR][4];
#pragma unroll
    for (int p = 0; p < NPAIR; ++p)
#pragma unroll
        for (int j = 0; j < 4; ++j) acc[p][j] = bias[j];

    gemm_pairs(acc, xb,  Wih2, tid);
    gemm_pairs(acc, hio, Whh2, tid);

    __syncthreads();   // all reads of xb/hio done before hio overwrite

#pragma unroll
    for (int p = 0; p < NPAIR; ++p) {
        float i0, i1, f0, f1, g0, g1, o0, o1;
        unpack2(acc[p][0], i0, i1);
        unpack2(acc[p][1], f0, f1);
        unpack2(acc[p][2], g0, g1);
        unpack2(acc[p][3], o0, o1);
        float c0 = sigf(f0) * cst[2 * p]     + sigf(i0) * tanhf(g0);
        float c1 = sigf(f1) * cst[2 * p + 1] + sigf(i1) * tanhf(g1);
        cst[2 * p]     = c0;
        cst[2 * p + 1] = c1;
        float h0 = sigf(o0) * tanhf(c0);
        float h1 = sigf(o1) * tanhf(c1);
        *(ull*)(hio + tid * XSTRIDE + p) = pack2(h0, h1);
    }
    __syncthreads();   // new h visible to all
}

__global__ __launch_bounds__(NTHREAD, 2)
void lstm_persistent_kernel(
    const float* __restrict__ history,   // (B, 60, 2)
    const float* __restrict__ emb_W,     // (128, 2)
    const float* __restrict__ emb_b,     // (128)
    const float* __restrict__ enc_bih,   // (2, 512)
    const float* __restrict__ enc_bhh,
    const float* __restrict__ dec_bih,
    const float* __restrict__ dec_bhh,
    const float* __restrict__ out_W,     // (2, 128)
    const float* __restrict__ out_b,     // (2)
    float* __restrict__ out)             // (B, 360, 2)
{
    __shared__ float2 xp [HDIM * XSTRIDE];
    __shared__ float2 hp0[HDIM * XSTRIDE];
    __shared__ float2 hp1[HDIM * XSTRIDE];
    __shared__ float  pred_sh[MROWS][2];
    __shared__ float  outw_sh[2][HDIM];
    __shared__ float  outb_sh[2];

    const int tid = threadIdx.x;
    const int b0  = blockIdx.x * MROWS;

    const float ew0 = emb_W[tid * 2 + 0];
    const float ew1 = emb_W[tid * 2 + 1];
    const float eb  = emb_b[tid];

    ull be0[4], be1[4], bd0[4], bd1[4];
#pragma unroll
    for (int j = 0; j < 4; ++j) {
        int g = tid + 128 * j;
        float v;
        v = enc_bih[g]       + enc_bhh[g];        be0[j] = dup2(v);
        v = enc_bih[512 + g] + enc_bhh[512 + g];  be1[j] = dup2(v);
        v = dec_bih[g]       + dec_bhh[g];        bd0[j] = dup2(v);
        v = dec_bih[512 + g] + dec_bhh[512 + g];  bd1[j] = dup2(v);
    }

    outw_sh[0][tid] = out_W[tid];
    outw_sh[1][tid] = out_W[128 + tid];
    if (tid < 2) outb_sh[tid] = out_b[tid];

    float cst0[MROWS], cst1[MROWS];
#pragma unroll
    for (int m = 0; m < MROWS; ++m) { cst0[m] = 0.0f; cst1[m] = 0.0f; }
#pragma unroll
    for (int p = 0; p < NPAIR; ++p) {
        hp0[tid * XSTRIDE + p] = make_float2(0.0f, 0.0f);
        hp1[tid * XSTRIDE + p] = make_float2(0.0f, 0.0f);
    }
    __syncthreads();

    const float2* eW0 = g_W2[0];
    const float2* eW1 = g_W2[1];
    const float2* eU0 = g_W2[2];
    const float2* eU1 = g_W2[3];
    const float2* dW0 = g_W2[4];
    const float2* dW1 = g_W2[5];
    const float2* dU0 = g_W2[6];
    const float2* dU1 = g_W2[7];

    // ---------------- Encoder: 60 steps ----------------
    for (int t = 0; t < T_HIST; ++t) {
#pragma unroll
        for (int p = 0; p < NPAIR; ++p) {
            const float* h0p = history + (size_t)(b0 + 2 * p)     * (T_HIST * 2) + t * 2;
            const float* h1p = history + (size_t)(b0 + 2 * p + 1) * (T_HIST * 2) + t * 2;
            float v0 = h0p[0] * ew0 + h0p[1] * ew1 + eb;
            float v1 = h1p[0] * ew0 + h1p[1] * ew1 + eb;
            *(ull*)(xp + tid * XSTRIDE + p) = pack2(v0, v1);
        }
        __syncthreads();

        lstm_layer(xp,  hp0, cst0, eW0, eU0, be0, tid);
        lstm_layer(hp0, hp1, cst1, eW1, eU1, be1, tid);
    }

    // ---------------- Decoder: 360 autoregressive steps ----------------
    const int wrp  = tid >> 5;
    const int lane = tid & 31;

    for (int t = 0; t < T_OUT; ++t) {
        if (t == 0) {
#pragma unroll
            for (int p = 0; p < NPAIR; ++p)
                xp[tid * XSTRIDE + p] = make_float2(0.0f, 0.0f);
        } else {
#pragma unroll
            for (int p = 0; p < NPAIR; ++p) {
                float v0 = pred_sh[2 * p][0]     * ew0 + pred_sh[2 * p][1]     * ew1 + eb;
                float v1 = pred_sh[2 * p + 1][0] * ew0 + pred_sh[2 * p + 1][1] * ew1 + eb;
                *(ull*)(xp + tid * XSTRIDE + p) = pack2(v0, v1);
            }
        }
        __syncthreads();

        lstm_layer(xp,  hp0, cst0, dW0, dU0, bd0, tid);
        lstm_layer(hp0, hp1, cst1, dW1, dU1, bd1, tid);

        // pred = h1 @ out_W.T + out_b ; 4 warps x 2 pairs each
#pragma unroll
        for (int pp = 0; pp < 2; ++pp) {
            int p = wrp + 4 * pp;
            float a00 = 0.0f, a01 = 0.0f, a10 = 0.0f, a11 = 0.0f;
#pragma unroll
            for (int j = 0; j < 4; ++j) {
                int k = lane + 32 * j;
                float2 hv = hp1[k * XSTRIDE + p];
                float w0 = outw_sh[0][k];
                float w1 = outw_sh[1][k];
                a00 += hv.x * w0;  a01 += hv.x * w1;
                a10 += hv.y * w0;  a11 += hv.y * w1;
            }
#pragma unroll
            for (int off = 16; off > 0; off >>= 1) {
                a00 += __shfl_xor_sync(0xffffffffu, a00, off);
                a01 += __shfl_xor_sync(0xffffffffu, a01, off);
                a10 += __shfl_xor_sync(0xffffffffu, a10, off);
                a11 += __shfl_xor_sync(0xffffffffu, a11, off);
            }
            if (lane == 0) {
                float p00 = a00 + outb_sh[0];
                float p01 = a01 + outb_sh[1];
                float p10 = a10 + outb_sh[0];
                float p11 = a11 + outb_sh[1];
                int m0 = 2 * p, m1 = 2 * p + 1;
                pred_sh[m0][0] = p00;  pred_sh[m0][1] = p01;
                pred_sh[m1][0] = p10;  pred_sh[m1][1] = p11;
                size_t o0 = (size_t)(b0 + m0) * (T_OUT * 2) + (size_t)t * 2;
                size_t o1 = (size_t)(b0 + m1) * (T_OUT * 2) + (size_t)t * 2;
                out[o0] = p00;  out[o0 + 1] = p01;
                out[o1] = p10;  out[o1 + 1] = p11;
            }
        }
        __syncthreads();   // pred_sh stable for next step
    }
}

extern "C" void kernel_launch(void* const* d_in, const int* in_sizes, int n_in,
                              void* d_out, int out_size)
{
    const float* history = (const float*)d_in[0];
    const float* emb_W   = (const float*)d_in[1];
    const float* emb_b   = (const float*)d_in[2];
    const float* enc_Wih = (const float*)d_in[3];
    const float* enc_Whh = (const float*)d_in[4];
    const float* enc_bih = (const float*)d_in[5];
    const float* enc_bhh = (const float*)d_in[6];
    const float* dec_Wih = (const float*)d_in[7];
    const float* dec_Whh = (const float*)d_in[8];
    const float* dec_bih = (const float*)d_in[9];
    const float* dec_bhh = (const float*)d_in[10];
    const float* out_W   = (const float*)d_in[11];
    const float* out_b   = (const float*)d_in[12];
    float* out = (float*)d_out;

    transpose_weights<<<1024, 256>>>(enc_Wih, enc_Whh, dec_Wih, dec_Whh);

    const int B = 4096;
    lstm_persistent_kernel<<<B / MROWS, NTHREAD>>>(
        history, emb_W, emb_b,
        enc_bih, enc_bhh, dec_bih, dec_bhh,
        out_W, out_b, out);
}

// round 12
// speedup vs baseline: 1.0770x; 1.0046x over previous
#include <cuda_runtime.h>
#include <math.h>

// SimpleLSTM: B=4096, T_HIST=60, D_IN=2, H=128, L=2, T_OUT=360
// Persistent kernel, MROWS=16 batch rows per block, grid=256.
// Weights pre-transposed to k-major (coalesced lane access), activations
// stored k-major as batch-row pairs, compute via packed fma.rn.f32x2.

#define MROWS   16
#define NPAIR   8          // MROWS/2
#define HDIM    128
#define NTHREAD 128
#define T_HIST  60
#define T_OUT   360
#define XSTRIDE 9          // padded row stride (float2) for k-major activations

typedef unsigned long long ull;

// Transposed weights: 8 mats (encWih0,encWih1,encWhh0,encWhh1,decWih0,decWih1,
// decWhh0,decWhh1), each [64 k-pairs][512 rows] float2 = {W[row][2k2],W[row][2k2+1]}
__device__ float2 g_W2[8][64 * 512];

__device__ __forceinline__ ull ffma2(ull a, ull b, ull c) {
    ull d;
    asm("fma.rn.f32x2 %0, %1, %2, %3;" : "=l"(d) : "l"(a), "l"(b), "l"(c));
    return d;
}
__device__ __forceinline__ ull dup2(float w) {
    ull d;
    asm("mov.b64 %0, {%1, %1};" : "=l"(d) : "f"(w));
    return d;
}
__device__ __forceinline__ ull pack2(float a, float b) {
    ull d;
    asm("mov.b64 %0, {%1, %2};" : "=l"(d) : "f"(a), "f"(b));
    return d;
}
__device__ __forceinline__ void unpack2(ull v, float& a, float& b) {
    asm("mov.b64 {%0, %1}, %2;" : "=f"(a), "=f"(b) : "l"(v));
}

__device__ __forceinline__ float sigf(float x) {
    return 1.0f / (1.0f + expf(-x));
}

// ---------------- weight transpose kernel ----------------
__global__ void transpose_weights(
    const float* __restrict__ eWih, const float* __restrict__ eWhh,
    const float* __restrict__ dWih, const float* __restrict__ dWhh)
{
    int idx = blockIdx.x * 256 + threadIdx.x;   // 0 .. 8*32768-1
    int mat = idx >> 15;
    int rem = idx & 32767;
    int k2  = rem >> 9;
    int row = rem & 511;
    int grp = mat >> 1;
    int lay = mat & 1;
    const float* src =
        (grp == 0 ? eWih : grp == 1 ? eWhh : grp == 2 ? dWih : dWhh) + lay * 65536;
    float a = src[row * 128 + 2 * k2];
    float b = src[row * 128 + 2 * k2 + 1];
    g_W2[mat][k2 * 512 + row] = make_float2(a, b);
}

// ---------------- gate GEMM on batch-row pairs ----------------
// acc[p][j] (f32x2, pair p = batch rows 2p,2p+1; j = gate i/f/g/o) +=
//   sum_k x[pair][k] * W[tid+128j][k]
__device__ __forceinline__ void gemm_pairs(
    ull (&acc)[NPAIR][4],
    const float2* __restrict__ xb,      // shared, k-major [128][XSTRIDE]
    const float2* __restrict__ W2,      // global, [64][512]
    int tid)
{
#pragma unroll 2
    for (int k2 = 0; k2 < 64; ++k2) {
        float2 w0 = W2[k2 * 512 + tid];
        float2 w1 = W2[k2 * 512 + tid + 128];
        float2 w2 = W2[k2 * 512 + tid + 256];
        float2 w3 = W2[k2 * 512 + tid + 384];

        const ull* x0 = (const ull*)(xb + (2 * k2)     * XSTRIDE);
        const ull* x1 = (const ull*)(xb + (2 * k2 + 1) * XSTRIDE);
        ull xa[NPAIR], xc[NPAIR];
#pragma unroll
        for (int p = 0; p < NPAIR; ++p) { xa[p] = x0[p]; xc[p] = x1[p]; }

        ull w0x = dup2(w0.x), w0y = dup2(w0.y);
        ull w1x = dup2(w1.x), w1y = dup2(w1.y);
        ull w2x = dup2(w2.x), w2y = dup2(w2.y);
        ull w3x = dup2(w3.x), w3y = dup2(w3.y);

#pragma unroll
        for (int p = 0; p < NPAIR; ++p) {
            acc[p][0] = ffma2(w0x, xa[p], acc[p][0]);
            acc[p][1] = ffma2(w1x, xa[p], acc[p][1]);
            acc[p][2] = ffma2(w2x, xa[p], acc[p][2]);
            acc[p][3] = ffma2(w3x, xa[p], acc[p][3]);
            acc[p][0] = ffma2(w0y, xc[p], acc[p][0]);
            acc[p][1] = ffma2(w1y, xc[p], acc[p][1]);
            acc[p][2] = ffma2(w2y, xc[p], acc[p][2]);
            acc[p][3] = ffma2(w3y, xc[p], acc[p][3]);
        }
    }
}

// One LSTM layer step. xb: input activations (k-major pairs), hio: this layer's
// h state (k-major pairs, updated in place), cst: c state (scalar regs).
__device__ __forceinline__ void lstm_layer(
    const float2* __restrict__ xb,
    float2* __restrict__ hio,
    float (&cst)[MROWS],
    const float2* __restrict__ Wih2,
    const float2* __restrict__ Whh2,
    const ull (&bias)[4],
    int tid)
{
    ull acc[NPAIR][4];
#pragma unroll
    for (int p = 0; p < NPAIR; ++p)
#pragma unroll
        for (int j = 0; j < 4; ++j) acc[p][j] = bias[j];

    gemm_pairs(acc, xb,  Wih2, tid);
    gemm_pairs(acc, hio, Whh2, tid);

    __syncthreads();   // all reads of xb/hio done before hio overwrite

#pragma unroll
    for (int p = 0; p < NPAIR; ++p) {
        float i0, i1, f0, f1, g0, g1, o0, o1;
        unpack2(acc[p][0], i0, i1);
        unpack2(acc[p][1], f0, f1);
        unpack2(acc[p][2], g0, g1);
        unpack2(acc[p][3], o0, o1);
        float c0 = sigf(f0) * cst[2 * p]     + sigf(i0) * tanhf(g0);
        float c1 = sigf(f1) * cst[2 * p + 1] + sigf(i1) * tanhf(g1);
        cst[2 * p]     = c0;
        cst[2 * p + 1] = c1;
        float h0 = sigf(o0) * tanhf(c0);
        float h1 = sigf(o1) * tanhf(c1);
        *(ull*)(hio + tid * XSTRIDE + p) = pack2(h0, h1);
    }
    __syncthreads();   // new h visible to all
}

__global__ __launch_bounds__(NTHREAD, 2)
void lstm_persistent_kernel(
    const float* __restrict__ history,   // (B, 60, 2)
    const float* __restrict__ emb_W,     // (128, 2)
    const float* __restrict__ emb_b,     // (128)
    const float* __restrict__ enc_bih,   // (2, 512)
    const float* __restrict__ enc_bhh,
    const float* __restrict__ dec_bih,
    const float* __restrict__ dec_bhh,
    const float* __restrict__ out_W,     // (2, 128)
    const float* __restrict__ out_b,     // (2)
    float* __restrict__ out)             // (B, 360, 2)
{
    __shared__ float2 xp [HDIM * XSTRIDE];
    __shared__ float2 hp0[HDIM * XSTRIDE];
    __shared__ float2 hp1[HDIM * XSTRIDE];
    __shared__ float  pred_sh[MROWS][2];
    __shared__ float  outw_sh[2][HDIM];
    __shared__ float  outb_sh[2];

    const int tid = threadIdx.x;
    const int b0  = blockIdx.x * MROWS;

    const float ew0 = emb_W[tid * 2 + 0];
    const float ew1 = emb_W[tid * 2 + 1];
    const float eb  = emb_b[tid];

    ull be0[4], be1[4], bd0[4], bd1[4];
#pragma unroll
    for (int j = 0; j < 4; ++j) {
        int g = tid + 128 * j;
        float v;
        v = enc_bih[g]       + enc_bhh[g];        be0[j] = dup2(v);
        v = enc_bih[512 + g] + enc_bhh[512 + g];  be1[j] = dup2(v);
        v = dec_bih[g]       + dec_bhh[g];        bd0[j] = dup2(v);
        v = dec_bih[512 + g] + dec_bhh[512 + g];  bd1[j] = dup2(v);
    }

    outw_sh[0][tid] = out_W[tid];
    outw_sh[1][tid] = out_W[128 + tid];
    if (tid < 2) outb_sh[tid] = out_b[tid];

    float cst0[MROWS], cst1[MROWS];
#pragma unroll
    for (int m = 0; m < MROWS; ++m) { cst0[m] = 0.0f; cst1[m] = 0.0f; }
#pragma unroll
    for (int p = 0; p < NPAIR; ++p) {
        hp0[tid * XSTRIDE + p] = make_float2(0.0f, 0.0f);
        hp1[tid * XSTRIDE + p] = make_float2(0.0f, 0.0f);
    }
    __syncthreads();

    const float2* eW0 = g_W2[0];
    const float2* eW1 = g_W2[1];
    const float2* eU0 = g_W2[2];
    const float2* eU1 = g_W2[3];
    const float2* dW0 = g_W2[4];
    const float2* dW1 = g_W2[5];
    const float2* dU0 = g_W2[6];
    const float2* dU1 = g_W2[7];

    // ---------------- Encoder: 60 steps ----------------
    for (int t = 0; t < T_HIST; ++t) {
#pragma unroll
        for (int p = 0; p < NPAIR; ++p) {
            const float* h0p = history + (size_t)(b0 + 2 * p)     * (T_HIST * 2) + t * 2;
            const float* h1p = history + (size_t)(b0 + 2 * p + 1) * (T_HIST * 2) + t * 2;
            float v0 = h0p[0] * ew0 + h0p[1] * ew1 + eb;
            float v1 = h1p[0] * ew0 + h1p[1] * ew1 + eb;
            *(ull*)(xp + tid * XSTRIDE + p) = pack2(v0, v1);
        }
        __syncthreads();

        lstm_layer(xp,  hp0, cst0, eW0, eU0, be0, tid);
        lstm_layer(hp0, hp1, cst1, eW1, eU1, be1, tid);
    }

    // ---------------- Decoder: 360 autoregressive steps ----------------
    const int wrp  = tid >> 5;
    const int lane = tid & 31;

    for (int t = 0; t < T_OUT; ++t) {
        if (t == 0) {
#pragma unroll
            for (int p = 0; p < NPAIR; ++p)
                xp[tid * XSTRIDE + p] = make_float2(0.0f, 0.0f);
        } else {
#pragma unroll
            for (int p = 0; p < NPAIR; ++p) {
                float v0 = pred_sh[2 * p][0]     * ew0 + pred_sh[2 * p][1]     * ew1 + eb;
                float v1 = pred_sh[2 * p + 1][0] * ew0 + pred_sh[2 * p + 1][1] * ew1 + eb;
                *(ull*)(xp + tid * XSTRIDE + p) = pack2(v0, v1);
            }
        }
        __syncthreads();

        lstm_layer(xp,  hp0, cst0, dW0, dU0, bd0, tid);
        lstm_layer(hp0, hp1, cst1, dW1, dU1, bd1, tid);

        // pred = h1 @ out_W.T + out_b ; 4 warps x 2 pairs each
#pragma unroll
        for (int pp = 0; pp < 2; ++pp) {
            int p = wrp + 4 * pp;
            float a00 = 0.0f, a01 = 0.0f, a10 = 0.0f, a11 = 0.0f;
#pragma unroll
            for (int j = 0; j < 4; ++j) {
                int k = lane + 32 * j;
                float2 hv = hp1[k * XSTRIDE + p];
                float w0 = outw_sh[0][k];
                float w1 = outw_sh[1][k];
                a00 += hv.x * w0;  a01 += hv.x * w1;
                a10 += hv.y * w0;  a11 += hv.y * w1;
            }
#pragma unroll
            for (int off = 16; off > 0; off >>= 1) {
                a00 += __shfl_xor_sync(0xffffffffu, a00, off);
                a01 += __shfl_xor_sync(0xffffffffu, a01, off);
                a10 += __shfl_xor_sync(0xffffffffu, a10, off);
                a11 += __shfl_xor_sync(0xffffffffu, a11, off);
            }
            if (lane == 0) {
                float p00 = a00 + outb_sh[0];
                float p01 = a01 + outb_sh[1];
                float p10 = a10 + outb_sh[0];
                float p11 = a11 + outb_sh[1];
                int m0 = 2 * p, m1 = 2 * p + 1;
                pred_sh[m0][0] = p00;  pred_sh[m0][1] = p01;
                pred_sh[m1][0] = p10;  pred_sh[m1][1] = p11;
                size_t o0 = (size_t)(b0 + m0) * (T_OUT * 2) + (size_t)t * 2;
                size_t o1 = (size_t)(b0 + m1) * (T_OUT * 2) + (size_t)t * 2;
                out[o0] = p00;  out[o0 + 1] = p01;
                out[o1] = p10;  out[o1 + 1] = p11;
            }
        }
        __syncthreads();   // pred_sh stable for next step
    }
}

extern "C" void kernel_launch(void* const* d_in, const int* in_sizes, int n_in,
                              void* d_out, int out_size)
{
    const float* history = (const float*)d_in[0];
    const float* emb_W   = (const float*)d_in[1];
    const float* emb_b   = (const float*)d_in[2];
    const float* enc_Wih = (const float*)d_in[3];
    const float* enc_Whh = (const float*)d_in[4];
    const float* enc_bih = (const float*)d_in[5];
    const float* enc_bhh = (const float*)d_in[6];
    const float* dec_Wih = (const float*)d_in[7];
    const float* dec_Whh = (const float*)d_in[8];
    const float* dec_bih = (const float*)d_in[9];
    const float* dec_bhh = (const float*)d_in[10];
    const float* out_W   = (const float*)d_in[11];
    const float* out_b   = (const float*)d_in[12];
    float* out = (float*)d_out;

    transpose_weights<<<1024, 256>>>(enc_Wih, enc_Whh, dec_Wih, dec_Whh);

    const int B = 4096;
    lstm_persistent_kernel<<<B / MROWS, NTHREAD>>>(
        history, emb_W, emb_b,
        enc_bih, enc_bhh, dec_bih, dec_bhh,
        out_W, out_b, out);
}

// round 13
// speedup vs baseline: 1.2670x; 1.1764x over previous
#include <cuda_runtime.h>
#include <math.h>

// SimpleLSTM: B=4096, T_HIST=60, D_IN=2, H=128, L=2, T_OUT=360
// Persistent kernel, MROWS=8 batch rows per block, grid=512, 4 CTAs/SM.
// Layer-0 input GEMM folded via rank-2 embedding identity:
//   Wih0 @ (p0*ew0 + p1*ew1 + eb) = p0*(Wih0@ew0) + p1*(Wih0@ew1) + (Wih0@eb)
// Weights pre-transposed k-major, compute in packed fma.rn.f32x2.

#define MROWS   8
#define NPAIR   4          // MROWS/2
#define HDIM    128
#define NTHREAD 128
#define T_HIST  60
#define T_OUT   360
#define XSTRIDE 5          // padded row stride (float2) for k-major activations

typedef unsigned long long ull;

// Transposed weights: mats 0:eWih0 1:eWih1 2:eWhh0 3:eWhh1 4:dWih0 5:dWih1
// 6:dWhh0 7:dWhh1, each [64 k-pairs][512 rows] float2
__device__ float2 g_W2[8][64 * 512];
// Rank-2 folded layer-0 input terms: [enc/dec][u0,u1,ub+bias][512 gate rows]
__device__ float  g_U[2][3][512];

__device__ __forceinline__ ull ffma2(ull a, ull b, ull c) {
    ull d;
    asm("fma.rn.f32x2 %0, %1, %2, %3;" : "=l"(d) : "l"(a), "l"(b), "l"(c));
    return d;
}
__device__ __forceinline__ ull dup2(float w) {
    ull d;
    asm("mov.b64 %0, {%1, %1};" : "=l"(d) : "f"(w));
    return d;
}
__device__ __forceinline__ ull pack2(float a, float b) {
    ull d;
    asm("mov.b64 %0, {%1, %2};" : "=l"(d) : "f"(a), "f"(b));
    return d;
}
__device__ __forceinline__ void unpack2(ull v, float& a, float& b) {
    asm("mov.b64 {%0, %1}, %2;" : "=f"(a), "=f"(b) : "l"(v));
}
__device__ __forceinline__ float sigf(float x) {
    return 1.0f / (1.0f + expf(-x));
}

// ---------------- prep kernel 1: weight transpose ----------------
__global__ void transpose_weights(
    const float* __restrict__ eWih, const float* __restrict__ eWhh,
    const float* __restrict__ dWih, const float* __restrict__ dWhh)
{
    int idx = blockIdx.x * 256 + threadIdx.x;   // 0 .. 8*32768-1
    int mat = idx >> 15;
    int rem = idx & 32767;
    int k2  = rem >> 9;
    int row = rem & 511;
    int grp = mat >> 1;
    int lay = mat & 1;
    const float* src =
        (grp == 0 ? eWih : grp == 1 ? eWhh : grp == 2 ? dWih : dWhh) + lay * 65536;
    float a = src[row * 128 + 2 * k2];
    float b = src[row * 128 + 2 * k2 + 1];
    g_W2[mat][k2 * 512 + row] = make_float2(a, b);
}

// ---------------- prep kernel 2: rank-2 folding of layer-0 Wih ----------------
__global__ void prep_rank2(
    const float* __restrict__ eWih, const float* __restrict__ dWih,
    const float* __restrict__ emb_W, const float* __restrict__ emb_b,
    const float* __restrict__ enc_bih, const float* __restrict__ enc_bhh,
    const float* __restrict__ dec_bih, const float* __restrict__ dec_bhh)
{
    int idx = blockIdx.x * 256 + threadIdx.x;   // 0..1023
    int mat = idx >> 9;                          // 0 enc, 1 dec
    int row = idx & 511;
    const float* W = (mat ? dWih : eWih) + row * 128;   // layer 0
    float a0 = 0.0f, a1 = 0.0f, ab = 0.0f;
    for (int k = 0; k < 128; ++k) {
        float w = W[k];
        a0 += w * emb_W[2 * k];
        a1 += w * emb_W[2 * k + 1];
        ab += w * emb_b[k];
    }
    const float* bi = mat ? dec_bih : enc_bih;
    const float* bh = mat ? dec_bhh : enc_bhh;
    g_U[mat][0][row] = a0;
    g_U[mat][1][row] = a1;
    g_U[mat][2][row] = ab + bi[row] + bh[row];
}

// ---------------- gate GEMM on batch-row pairs ----------------
__device__ __forceinline__ void gemm_pairs(
    ull (&acc)[NPAIR][4],
    const float2* __restrict__ xb,      // shared, k-major [128][XSTRIDE]
    const float2* __restrict__ W2,      // global, [64][512]
    int tid)
{
#pragma unroll 2
    for (int k2 = 0; k2 < 64; ++k2) {
        float2 w0 = W2[k2 * 512 + tid];
        float2 w1 = W2[k2 * 512 + tid + 128];
        float2 w2 = W2[k2 * 512 + tid + 256];
        float2 w3 = W2[k2 * 512 + tid + 384];

        const ull* x0 = (const ull*)(xb + (2 * k2)     * XSTRIDE);
        const ull* x1 = (const ull*)(xb + (2 * k2 + 1) * XSTRIDE);
        ull xa[NPAIR], xc[NPAIR];
#pragma unroll
        for (int p = 0; p < NPAIR; ++p) { xa[p] = x0[p]; xc[p] = x1[p]; }

        ull w0x = dup2(w0.x), w0y = dup2(w0.y);
        ull w1x = dup2(w1.x), w1y = dup2(w1.y);
        ull w2x = dup2(w2.x), w2y = dup2(w2.y);
        ull w3x = dup2(w3.x), w3y = dup2(w3.y);

#pragma unroll
        for (int p = 0; p < NPAIR; ++p) {
            acc[p][0] = ffma2(w0x, xa[p], acc[p][0]);
            acc[p][1] = ffma2(w1x, xa[p], acc[p][1]);
            acc[p][2] = ffma2(w2x, xa[p], acc[p][2]);
            acc[p][3] = ffma2(w3x, xa[p], acc[p][3]);
            acc[p][0] = ffma2(w0y, xc[p], acc[p][0]);
            acc[p][1] = ffma2(w1y, xc[p], acc[p][1]);
            acc[p][2] = ffma2(w2y, xc[p], acc[p][2]);
            acc[p][3] = ffma2(w3y, xc[p], acc[p][3]);
        }
    }
}

// Gate nonlinearity + state update. Sync before (protect readers of hio),
// sync after (publish new h).
__device__ __forceinline__ void gate_update(
    ull (&acc)[NPAIR][4],
    float2* __restrict__ hio,
    float (&cst)[MROWS],
    int tid)
{
    __syncthreads();
#pragma unroll
    for (int p = 0; p < NPAIR; ++p) {
        float i0, i1, f0, f1, g0, g1, o0, o1;
        unpack2(acc[p][0], i0, i1);
        unpack2(acc[p][1], f0, f1);
        unpack2(acc[p][2], g0, g1);
        unpack2(acc[p][3], o0, o1);
        float c0 = sigf(f0) * cst[2 * p]     + sigf(i0) * tanhf(g0);
        float c1 = sigf(f1) * cst[2 * p + 1] + sigf(i1) * tanhf(g1);
        cst[2 * p]     = c0;
        cst[2 * p + 1] = c1;
        float h0 = sigf(o0) * tanhf(c0);
        float h1 = sigf(o1) * tanhf(c1);
        *(ull*)(hio + tid * XSTRIDE + p) = pack2(h0, h1);
    }
    __syncthreads();
}

__global__ __launch_bounds__(NTHREAD, 4)
void lstm_persistent_kernel(
    const float* __restrict__ history,   // (B, 60, 2)
    const float* __restrict__ enc_bih,   // (2, 512)
    const float* __restrict__ enc_bhh,
    const float* __restrict__ dec_bih,
    const float* __restrict__ dec_bhh,
    const float* __restrict__ out_W,     // (2, 128)
    const float* __restrict__ out_b,     // (2)
    float* __restrict__ out)             // (B, 360, 2)
{
    __shared__ float2 hp0[HDIM * XSTRIDE];
    __shared__ float2 hp1[HDIM * XSTRIDE];
    __shared__ float  hist_sh[T_HIST * MROWS * 2];   // [t][row][d]
    __shared__ float  pred_sh[MROWS][2];
    __shared__ float  outw_sh[2][HDIM];
    __shared__ float  outb_sh[2];

    const int tid = threadIdx.x;
    const int b0  = blockIdx.x * MROWS;

    // Layer-1 combined biases + decoder layer-0 plain bias (for t==0, x=0)
    float be1[4], bd1[4], bd0[4];
#pragma unroll
    for (int j = 0; j < 4; ++j) {
        int g = tid + 128 * j;
        be1[j] = enc_bih[512 + g] + enc_bhh[512 + g];
        bd1[j] = dec_bih[512 + g] + dec_bhh[512 + g];
        bd0[j] = dec_bih[g]       + dec_bhh[g];
    }

    outw_sh[0][tid] = out_W[tid];
    outw_sh[1][tid] = out_W[128 + tid];
    if (tid < 2) outb_sh[tid] = out_b[tid];

    // Preload this block's entire history window (coalesced)
    for (int g = tid; g < T_HIST * MROWS * 2; g += NTHREAD) {
        int row = g / (T_HIST * 2);
        int r   = g - row * (T_HIST * 2);    // t*2 + d
        hist_sh[(r >> 1) * (MROWS * 2) + row * 2 + (r & 1)] =
            history[(size_t)(b0 + row) * (T_HIST * 2) + r];
    }

    float cst0[MROWS], cst1[MROWS];
#pragma unroll
    for (int m = 0; m < MROWS; ++m) { cst0[m] = 0.0f; cst1[m] = 0.0f; }
#pragma unroll
    for (int p = 0; p < NPAIR; ++p) {
        hp0[tid * XSTRIDE + p] = make_float2(0.0f, 0.0f);
        hp1[tid * XSTRIDE + p] = make_float2(0.0f, 0.0f);
    }
    __syncthreads();

    const float2* eU0 = g_W2[2];   // enc layer0 Whh
    const float2* eW1 = g_W2[1];   // enc layer1 Wih
    const float2* eU1 = g_W2[3];   // enc layer1 Whh
    const float2* dU0 = g_W2[6];   // dec layer0 Whh
    const float2* dW1 = g_W2[5];   // dec layer1 Wih
    const float2* dU1 = g_W2[7];   // dec layer1 Whh

    const float* UE0 = &g_U[0][0][0];
    const float* UE1 = &g_U[0][1][0];
    const float* UEb = &g_U[0][2][0];
    const float* UD0 = &g_U[1][0][0];
    const float* UD1 = &g_U[1][1][0];
    const float* UDb = &g_U[1][2][0];

    ull acc[NPAIR][4];

    // ---------------- Encoder: 60 steps ----------------
    for (int t = 0; t < T_HIST; ++t) {
        // Layer 0: rank-2 input term + Whh GEMM
        {
            const float* hs = hist_sh + t * (MROWS * 2);
            ull pp0[NPAIR], pp1[NPAIR];
#pragma unroll
            for (int p = 0; p < NPAIR; ++p) {
                pp0[p] = pack2(hs[4 * p],     hs[4 * p + 2]);
                pp1[p] = pack2(hs[4 * p + 1], hs[4 * p + 3]);
            }
#pragma unroll
            for (int j = 0; j < 4; ++j) {
                int g = tid + 128 * j;
                ull a0 = dup2(UE0[g]);
                ull a1 = dup2(UE1[g]);
                ull ab = dup2(UEb[g]);
#pragma unroll
                for (int p = 0; p < NPAIR; ++p)
                    acc[p][j] = ffma2(a0, pp0[p], ffma2(a1, pp1[p], ab));
            }
        }
        gemm_pairs(acc, hp0, eU0, tid);
        gate_update(acc, hp0, cst0, tid);

        // Layer 1
#pragma unroll
        for (int j = 0; j < 4; ++j) {
            ull b = dup2(be1[j]);
#pragma unroll
            for (int p = 0; p < NPAIR; ++p) acc[p][j] = b;
        }
        gemm_pairs(acc, hp0, eW1, tid);
        gemm_pairs(acc, hp1, eU1, tid);
        gate_update(acc, hp1, cst1, tid);
    }

    // ---------------- Decoder: 360 autoregressive steps ----------------
    const int wrp  = tid >> 5;
    const int lane = tid & 31;

    for (int t = 0; t < T_OUT; ++t) {
        // Layer 0: rank-2 input term (pred feedback) + Whh GEMM
        if (t == 0) {
#pragma unroll
            for (int j = 0; j < 4; ++j) {
                ull b = dup2(bd0[j]);
#pragma unroll
                for (int p = 0; p < NPAIR; ++p) acc[p][j] = b;
            }
        } else {
            ull pp0[NPAIR], pp1[NPAIR];
#pragma unroll
            for (int p = 0; p < NPAIR; ++p) {
                pp0[p] = pack2(pred_sh[2 * p][0], pred_sh[2 * p + 1][0]);
                pp1[p] = pack2(pred_sh[2 * p][1], pred_sh[2 * p + 1][1]);
            }
#pragma unroll
            for (int j = 0; j < 4; ++j) {
                int g = tid + 128 * j;
                ull a0 = dup2(UD0[g]);
                ull a1 = dup2(UD1[g]);
                ull ab = dup2(UDb[g]);
#pragma unroll
                for (int p = 0; p < NPAIR; ++p)
                    acc[p][j] = ffma2(a0, pp0[p], ffma2(a1, pp1[p], ab));
            }
        }
        gemm_pairs(acc, hp0, dU0, tid);
        gate_update(acc, hp0, cst0, tid);

        // Layer 1
#pragma unroll
        for (int j = 0; j < 4; ++j) {
            ull b = dup2(bd1[j]);
#pragma unroll
            for (int p = 0; p < NPAIR; ++p) acc[p][j] = b;
        }
        gemm_pairs(acc, hp0, dW1, tid);
        gemm_pairs(acc, hp1, dU1, tid);
        gate_update(acc, hp1, cst1, tid);

        // pred = h1 @ out_W.T + out_b ; warp w handles pair p=w
        {
            int p = wrp;
            float a00 = 0.0f, a01 = 0.0f, a10 = 0.0f, a11 = 0.0f;
#pragma unroll
            for (int j = 0; j < 4; ++j) {
                int k = lane + 32 * j;
                float2 hv = hp1[k * XSTRIDE + p];
                float w0 = outw_sh[0][k];
                float w1 = outw_sh[1][k];
                a00 += hv.x * w0;  a01 += hv.x * w1;
                a10 += hv.y * w0;  a11 += hv.y * w1;
            }
#pragma unroll
            for (int off = 16; off > 0; off >>= 1) {
                a00 += __shfl_xor_sync(0xffffffffu, a00, off);
                a01 += __shfl_xor_sync(0xffffffffu, a01, off);
                a10 += __shfl_xor_sync(0xffffffffu, a10, off);
                a11 += __shfl_xor_sync(0xffffffffu, a11, off);
            }
            if (lane == 0) {
                float p00 = a00 + outb_sh[0];
                float p01 = a01 + outb_sh[1];
                float p10 = a10 + outb_sh[0];
                float p11 = a11 + outb_sh[1];
                int m0 = 2 * p, m1 = 2 * p + 1;
                pred_sh[m0][0] = p00;  pred_sh[m0][1] = p01;
                pred_sh[m1][0] = p10;  pred_sh[m1][1] = p11;
                size_t o0 = (size_t)(b0 + m0) * (T_OUT * 2) + (size_t)t * 2;
                size_t o1 = (size_t)(b0 + m1) * (T_OUT * 2) + (size_t)t * 2;
                out[o0] = p00;  out[o0 + 1] = p01;
                out[o1] = p10;  out[o1 + 1] = p11;
            }
        }
        __syncthreads();   // pred_sh stable for next step
    }
}

extern "C" void kernel_launch(void* const* d_in, const int* in_sizes, int n_in,
                              void* d_out, int out_size)
{
    const float* history = (const float*)d_in[0];
    const float* emb_W   = (const float*)d_in[1];
    const float* emb_b   = (const float*)d_in[2];
    const float* enc_Wih = (const float*)d_in[3];
    const float* enc_Whh = (const float*)d_in[4];
    const float* enc_bih = (const float*)d_in[5];
    const float* enc_bhh = (const float*)d_in[6];
    const float* dec_Wih = (const float*)d_in[7];
    const float* dec_Whh = (const float*)d_in[8];
    const float* dec_bih = (const float*)d_in[9];
    const float* dec_bhh = (const float*)d_in[10];
    const float* out_W   = (const float*)d_in[11];
    const float* out_b   = (const float*)d_in[12];
    float* out = (float*)d_out;

    transpose_weights<<<1024, 256>>>(enc_Wih, enc_Whh, dec_Wih, dec_Whh);
    prep_rank2<<<4, 256>>>(enc_Wih, dec_Wih, emb_W, emb_b,
                           enc_bih, enc_bhh, dec_bih, dec_bhh);

    const int B = 4096;
    lstm_persistent_kernel<<<B / MROWS, NTHREAD>>>(
        history, enc_bih, enc_bhh, dec_bih, dec_bhh,
        out_W, out_b, out);
}

// round 14
// speedup vs baseline: 1.3648x; 1.0772x over previous
#include <cuda_runtime.h>
#include <math.h>

// SimpleLSTM: B=4096, T_HIST=60, D_IN=2, H=128, L=2, T_OUT=360
// Persistent kernel, MROWS=8 rows/block, grid=512, 4 CTAs/SM.
// Rank-2 embedding fold for layer-0 input GEMM; k-major transposed weights;
// packed fma.rn.f32x2 compute; MUFU-based fast sigmoid/tanh.

#define MROWS   8
#define NPAIR   4          // MROWS/2
#define HDIM    128
#define NTHREAD 128
#define T_HIST  60
#define T_OUT   360
#define XSTRIDE 5          // padded row stride (float2) for k-major activations

typedef unsigned long long ull;

// Transposed weights: mats 0:eWih0 1:eWih1 2:eWhh0 3:eWhh1 4:dWih0 5:dWih1
// 6:dWhh0 7:dWhh1, each [64 k-pairs][512 rows] float2
__device__ float2 g_W2[8][64 * 512];
// Rank-2 folded layer-0 input terms: [enc/dec][u0,u1,ub+bias][512 gate rows]
__device__ float  g_U[2][3][512];

__device__ __forceinline__ ull ffma2(ull a, ull b, ull c) {
    ull d;
    asm("fma.rn.f32x2 %0, %1, %2, %3;" : "=l"(d) : "l"(a), "l"(b), "l"(c));
    return d;
}
__device__ __forceinline__ ull dup2(float w) {
    ull d;
    asm("mov.b64 %0, {%1, %1};" : "=l"(d) : "f"(w));
    return d;
}
__device__ __forceinline__ ull pack2(float a, float b) {
    ull d;
    asm("mov.b64 %0, {%1, %2};" : "=l"(d) : "f"(a), "f"(b));
    return d;
}
__device__ __forceinline__ void unpack2(ull v, float& a, float& b) {
    asm("mov.b64 {%0, %1}, %2;" : "=f"(a), "=f"(b) : "l"(v));
}

// Fast sigmoid / tanh via MUFU ex2 + rcp (rel err ~1e-6, |x| bounded by
// gate preactivations which are O(few) here).
__device__ __forceinline__ float sigf(float x) {
    float e = __expf(-x);
    return __fdividef(1.0f, 1.0f + e);
}
__device__ __forceinline__ float tanh_fast(float x) {
    float e = __expf(-2.0f * x);
    return __fdividef(1.0f - e, 1.0f + e);
}

// ---------------- prep kernel 1: weight transpose ----------------
__global__ void transpose_weights(
    const float* __restrict__ eWih, const float* __restrict__ eWhh,
    const float* __restrict__ dWih, const float* __restrict__ dWhh)
{
    int idx = blockIdx.x * 256 + threadIdx.x;   // 0 .. 8*32768-1
    int mat = idx >> 15;
    int rem = idx & 32767;
    int k2  = rem >> 9;
    int row = rem & 511;
    int grp = mat >> 1;
    int lay = mat & 1;
    const float* src =
        (grp == 0 ? eWih : grp == 1 ? eWhh : grp == 2 ? dWih : dWhh) + lay * 65536;
    float a = src[row * 128 + 2 * k2];
    float b = src[row * 128 + 2 * k2 + 1];
    g_W2[mat][k2 * 512 + row] = make_float2(a, b);
}

// ---------------- prep kernel 2: rank-2 folding of layer-0 Wih ----------------
__global__ void prep_rank2(
    const float* __restrict__ eWih, const float* __restrict__ dWih,
    const float* __restrict__ emb_W, const float* __restrict__ emb_b,
    const float* __restrict__ enc_bih, const float* __restrict__ enc_bhh,
    const float* __restrict__ dec_bih, const float* __restrict__ dec_bhh)
{
    int idx = blockIdx.x * 256 + threadIdx.x;   // 0..1023
    int mat = idx >> 9;                          // 0 enc, 1 dec
    int row = idx & 511;
    const float* W = (mat ? dWih : eWih) + row * 128;   // layer 0
    float a0 = 0.0f, a1 = 0.0f, ab = 0.0f;
    for (int k = 0; k < 128; ++k) {
        float w = W[k];
        a0 += w * emb_W[2 * k];
        a1 += w * emb_W[2 * k + 1];
        ab += w * emb_b[k];
    }
    const float* bi = mat ? dec_bih : enc_bih;
    const float* bh = mat ? dec_bhh : enc_bhh;
    g_U[mat][0][row] = a0;
    g_U[mat][1][row] = a1;
    g_U[mat][2][row] = ab + bi[row] + bh[row];
}

// ---------------- gate GEMM on batch-row pairs ----------------
// Weight dups regenerated per half-group (2 gates at a time) to cap live regs.
__device__ __forceinline__ void gemm_pairs(
    ull (&acc)[NPAIR][4],
    const float2* __restrict__ xb,      // shared, k-major [128][XSTRIDE]
    const float2* __restrict__ W2,      // global, [64][512]
    int tid)
{
#pragma unroll 2
    for (int k2 = 0; k2 < 64; ++k2) {
        float2 w0 = W2[k2 * 512 + tid];
        float2 w1 = W2[k2 * 512 + tid + 128];
        float2 w2 = W2[k2 * 512 + tid + 256];
        float2 w3 = W2[k2 * 512 + tid + 384];

        const ull* x0 = (const ull*)(xb + (2 * k2)     * XSTRIDE);
        const ull* x1 = (const ull*)(xb + (2 * k2 + 1) * XSTRIDE);
        ull xa[NPAIR], xc[NPAIR];
#pragma unroll
        for (int p = 0; p < NPAIR; ++p) { xa[p] = x0[p]; xc[p] = x1[p]; }

        // gates 0,1
        {
            ull a0 = dup2(w0.x), a1 = dup2(w1.x);
            ull b0 = dup2(w0.y), b1 = dup2(w1.y);
#pragma unroll
            for (int p = 0; p < NPAIR; ++p) {
                acc[p][0] = ffma2(a0, xa[p], acc[p][0]);
                acc[p][1] = ffma2(a1, xa[p], acc[p][1]);
                acc[p][0] = ffma2(b0, xc[p], acc[p][0]);
                acc[p][1] = ffma2(b1, xc[p], acc[p][1]);
            }
        }
        // gates 2,3
        {
            ull a2 = dup2(w2.x), a3 = dup2(w3.x);
            ull b2 = dup2(w2.y), b3 = dup2(w3.y);
#pragma unroll
            for (int p = 0; p < NPAIR; ++p) {
                acc[p][2] = ffma2(a2, xa[p], acc[p][2]);
                acc[p][3] = ffma2(a3, xa[p], acc[p][3]);
                acc[p][2] = ffma2(b2, xc[p], acc[p][2]);
                acc[p][3] = ffma2(b3, xc[p], acc[p][3]);
            }
        }
    }
}

// Gate nonlinearity + state update.
__device__ __forceinline__ void gate_update(
    ull (&acc)[NPAIR][4],
    float2* __restrict__ hio,
    float (&cst)[MROWS],
    int tid)
{
    __syncthreads();
#pragma unroll
    for (int p = 0; p < NPAIR; ++p) {
        float i0, i1, f0, f1, g0, g1, o0, o1;
        unpack2(acc[p][0], i0, i1);
        unpack2(acc[p][1], f0, f1);
        unpack2(acc[p][2], g0, g1);
        unpack2(acc[p][3], o0, o1);
        float c0 = sigf(f0) * cst[2 * p]     + sigf(i0) * tanh_fast(g0);
        float c1 = sigf(f1) * cst[2 * p + 1] + sigf(i1) * tanh_fast(g1);
        cst[2 * p]     = c0;
        cst[2 * p + 1] = c1;
        float h0 = sigf(o0) * tanh_fast(c0);
        float h1 = sigf(o1) * tanh_fast(c1);
        *(ull*)(hio + tid * XSTRIDE + p) = pack2(h0, h1);
    }
    __syncthreads();
}

__global__ __launch_bounds__(NTHREAD, 4)
void lstm_persistent_kernel(
    const float* __restrict__ history,   // (B, 60, 2)
    const float* __restrict__ enc_bih,   // (2, 512)
    const float* __restrict__ enc_bhh,
    const float* __restrict__ dec_bih,
    const float* __restrict__ dec_bhh,
    const float* __restrict__ out_W,     // (2, 128)
    const float* __restrict__ out_b,     // (2)
    float* __restrict__ out)             // (B, 360, 2)
{
    __shared__ float2 hp0[HDIM * XSTRIDE];
    __shared__ float2 hp1[HDIM * XSTRIDE];
    __shared__ float  hist_sh[T_HIST * MROWS * 2];   // [t][row][d]
    __shared__ float  U_sh[2][3][512];               // rank-2 vectors (enc,dec)
    __shared__ float  b1_sh[2][512];                 // layer-1 biases (enc,dec)
    __shared__ float  bd0_sh[512];                   // dec layer-0 plain bias
    __shared__ float  pred_sh[MROWS][2];
    __shared__ float  outw_sh[2][HDIM];
    __shared__ float  outb_sh[2];

    const int tid = threadIdx.x;
    const int b0  = blockIdx.x * MROWS;

    // Stage small constants into shared (frees ~30 regs vs keeping dup'd)
    for (int g = tid; g < 512; g += NTHREAD) {
        U_sh[0][0][g] = g_U[0][0][g];
        U_sh[0][1][g] = g_U[0][1][g];
        U_sh[0][2][g] = g_U[0][2][g];
        U_sh[1][0][g] = g_U[1][0][g];
        U_sh[1][1][g] = g_U[1][1][g];
        U_sh[1][2][g] = g_U[1][2][g];
        b1_sh[0][g] = enc_bih[512 + g] + enc_bhh[512 + g];
        b1_sh[1][g] = dec_bih[512 + g] + dec_bhh[512 + g];
        bd0_sh[g]   = dec_bih[g]       + dec_bhh[g];
    }

    outw_sh[0][tid] = out_W[tid];
    outw_sh[1][tid] = out_W[128 + tid];
    if (tid < 2) outb_sh[tid] = out_b[tid];

    // Preload this block's history window (coalesced)
    for (int g = tid; g < T_HIST * MROWS * 2; g += NTHREAD) {
        int row = g / (T_HIST * 2);
        int r   = g - row * (T_HIST * 2);    // t*2 + d
        hist_sh[(r >> 1) * (MROWS * 2) + row * 2 + (r & 1)] =
            history[(size_t)(b0 + row) * (T_HIST * 2) + r];
    }

    float cst0[MROWS], cst1[MROWS];
#pragma unroll
    for (int m = 0; m < MROWS; ++m) { cst0[m] = 0.0f; cst1[m] = 0.0f; }
#pragma unroll
    for (int p = 0; p < NPAIR; ++p) {
        hp0[tid * XSTRIDE + p] = make_float2(0.0f, 0.0f);
        hp1[tid * XSTRIDE + p] = make_float2(0.0f, 0.0f);
    }
    __syncthreads();

    const float2* eU0 = g_W2[2];   // enc layer0 Whh
    const float2* eW1 = g_W2[1];   // enc layer1 Wih
    const float2* eU1 = g_W2[3];   // enc layer1 Whh
    const float2* dU0 = g_W2[6];   // dec layer0 Whh
    const float2* dW1 = g_W2[5];   // dec layer1 Wih
    const float2* dU1 = g_W2[7];   // dec layer1 Whh

    ull acc[NPAIR][4];

    // ---------------- Encoder: 60 steps ----------------
    for (int t = 0; t < T_HIST; ++t) {
        // Layer 0: rank-2 input term + Whh GEMM
        {
            const float* hs = hist_sh + t * (MROWS * 2);
            ull pp0[NPAIR], pp1[NPAIR];
#pragma unroll
            for (int p = 0; p < NPAIR; ++p) {
                pp0[p] = pack2(hs[4 * p],     hs[4 * p + 2]);
                pp1[p] = pack2(hs[4 * p + 1], hs[4 * p + 3]);
            }
#pragma unroll
            for (int j = 0; j < 4; ++j) {
                int g = tid + 128 * j;
                ull a0 = dup2(U_sh[0][0][g]);
                ull a1 = dup2(U_sh[0][1][g]);
                ull ab = dup2(U_sh[0][2][g]);
#pragma unroll
                for (int p = 0; p < NPAIR; ++p)
                    acc[p][j] = ffma2(a0, pp0[p], ffma2(a1, pp1[p], ab));
            }
        }
        gemm_pairs(acc, hp0, eU0, tid);
        gate_update(acc, hp0, cst0, tid);

        // Layer 1
#pragma unroll
        for (int j = 0; j < 4; ++j) {
            ull b = dup2(b1_sh[0][tid + 128 * j]);
#pragma unroll
            for (int p = 0; p < NPAIR; ++p) acc[p][j] = b;
        }
        gemm_pairs(acc, hp0, eW1, tid);
        gemm_pairs(acc, hp1, eU1, tid);
        gate_update(acc, hp1, cst1, tid);
    }

    // ---------------- Decoder: 360 autoregressive steps ----------------
    const int wrp  = tid >> 5;
    const int lane = tid & 31;

    for (int t = 0; t < T_OUT; ++t) {
        // Layer 0: rank-2 input term (pred feedback) + Whh GEMM
        if (t == 0) {
#pragma unroll
            for (int j = 0; j < 4; ++j) {
                ull b = dup2(bd0_sh[tid + 128 * j]);
#pragma unroll
                for (int p = 0; p < NPAIR; ++p) acc[p][j] = b;
            }
        } else {
            ull pp0[NPAIR], pp1[NPAIR];
#pragma unroll
            for (int p = 0; p < NPAIR; ++p) {
                pp0[p] = pack2(pred_sh[2 * p][0], pred_sh[2 * p + 1][0]);
                pp1[p] = pack2(pred_sh[2 * p][1], pred_sh[2 * p + 1][1]);
            }
#pragma unroll
            for (int j = 0; j < 4; ++j) {
                int g = tid + 128 * j;
                ull a0 = dup2(U_sh[1][0][g]);
                ull a1 = dup2(U_sh[1][1][g]);
                ull ab = dup2(U_sh[1][2][g]);
#pragma unroll
                for (int p = 0; p < NPAIR; ++p)
                    acc[p][j] = ffma2(a0, pp0[p], ffma2(a1, pp1[p], ab));
            }
        }
        gemm_pairs(acc, hp0, dU0, tid);
        gate_update(acc, hp0, cst0, tid);

        // Layer 1
#pragma unroll
        for (int j = 0; j < 4; ++j) {
            ull b = dup2(b1_sh[1][tid + 128 * j]);
#pragma unroll
            for (int p = 0; p < NPAIR; ++p) acc[p][j] = b;
        }
        gemm_pairs(acc, hp0, dW1, tid);
        gemm_pairs(acc, hp1, dU1, tid);
        gate_update(acc, hp1, cst1, tid);

        // pred = h1 @ out_W.T + out_b ; warp w handles pair p=w
        {
            int p = wrp;
            float a00 = 0.0f, a01 = 0.0f, a10 = 0.0f, a11 = 0.0f;
#pragma unroll
            for (int j = 0; j < 4; ++j) {
                int k = lane + 32 * j;
                float2 hv = hp1[k * XSTRIDE + p];
                float w0 = outw_sh[0][k];
                float w1 = outw_sh[1][k];
                a00 += hv.x * w0;  a01 += hv.x * w1;
                a10 += hv.y * w0;  a11 += hv.y * w1;
            }
#pragma unroll
            for (int off = 16; off > 0; off >>= 1) {
                a00 += __shfl_xor_sync(0xffffffffu, a00, off);
                a01 += __shfl_xor_sync(0xffffffffu, a01, off);
                a10 += __shfl_xor_sync(0xffffffffu, a10, off);
                a11 += __shfl_xor_sync(0xffffffffu, a11, off);
            }
            if (lane == 0) {
                float p00 = a00 + outb_sh[0];
                float p01 = a01 + outb_sh[1];
                float p10 = a10 + outb_sh[0];
                float p11 = a11 + outb_sh[1];
                int m0 = 2 * p, m1 = 2 * p + 1;
                pred_sh[m0][0] = p00;  pred_sh[m0][1] = p01;
                pred_sh[m1][0] = p10;  pred_sh[m1][1] = p11;
                size_t o0 = (size_t)(b0 + m0) * (T_OUT * 2) + (size_t)t * 2;
                size_t o1 = (size_t)(b0 + m1) * (T_OUT * 2) + (size_t)t * 2;
                out[o0] = p00;  out[o0 + 1] = p01;
                out[o1] = p10;  out[o1 + 1] = p11;
            }
        }
        __syncthreads();   // pred_sh stable for next step
    }
}

extern "C" void kernel_launch(void* const* d_in, const int* in_sizes, int n_in,
                              void* d_out, int out_size)
{
    const float* history = (const float*)d_in[0];
    const float* emb_W   = (const float*)d_in[1];
    const float* emb_b   = (const float*)d_in[2];
    const float* enc_Wih = (const float*)d_in[3];
    const float* enc_Whh = (const float*)d_in[4];
    const float* enc_bih = (const float*)d_in[5];
    const float* enc_bhh = (const float*)d_in[6];
    const float* dec_Wih = (const float*)d_in[7];
    const float* dec_Whh = (const float*)d_in[8];
    const float* dec_bih = (const float*)d_in[9];
    const float* dec_bhh = (const float*)d_in[10];
    const float* out_W   = (const float*)d_in[11];
    const float* out_b   = (const float*)d_in[12];
    float* out = (float*)d_out;

    transpose_weights<<<1024, 256>>>(enc_Wih, enc_Whh, dec_Wih, dec_Whh);
    prep_rank2<<<4, 256>>>(enc_Wih, dec_Wih, emb_W, emb_b,
                           enc_bih, enc_bhh, dec_bih, dec_bhh);

    const int B = 4096;
    lstm_persistent_kernel<<<B / MROWS, NTHREAD>>>(
        history, enc_bih, enc_bhh, dec_bih, dec_bhh,
        out_W, out_b, out);
}

// round 15
// speedup vs baseline: 1.6277x; 1.1927x over previous
#include <cuda_runtime.h>
#include <math.h>

// SimpleLSTM: B=4096, T_HIST=60, D_IN=2, H=128, L=2, T_OUT=360
// Persistent kernel, MROWS=8 rows/block, grid=512, 4 CTAs/SM.
// Rank-2 embedding fold; float4-packed k-major weights (2x LDG.128/k2);
// vectorized x loads (LDS.128); double-buffered h states (fewer barriers);
// packed fma.rn.f32x2; MUFU fast sigmoid/tanh.

#define MROWS   8
#define NPAIR   4          // MROWS/2
#define HDIM    128
#define NTHREAD 128
#define T_HIST  60
#define T_OUT   360
#define XSTRIDE 6          // padded row stride (float2), 48B (16B-aligned rows)

typedef unsigned long long ull;

// Packed transposed weights: mats 0:eWih0 1:eWih1 2:eWhh0 3:eWhh1 4:dWih0
// 5:dWih1 6:dWhh0 7:dWhh1. Layout [mat][k2*256 + gp*128 + tid] float4 =
// (W[r0][2k2], W[r0][2k2+1], W[r1][2k2], W[r1][2k2+1]), r0=gp*256+tid, r1=r0+128.
__device__ float4 g_W4[8][64 * 256];
// Rank-2 folded layer-0 input terms: [enc/dec][u0,u1,ub+bias][512 gate rows]
__device__ float  g_U[2][3][512];
// Combined layer-1 biases [enc/dec][512]; decoder layer-0 plain bias [512]
__device__ float  g_B1[2][512];
__device__ float  g_BD0[512];

__device__ __forceinline__ ull ffma2(ull a, ull b, ull c) {
    ull d;
    asm("fma.rn.f32x2 %0, %1, %2, %3;" : "=l"(d) : "l"(a), "l"(b), "l"(c));
    return d;
}
__device__ __forceinline__ ull dup2(float w) {
    ull d;
    asm("mov.b64 %0, {%1, %1};" : "=l"(d) : "f"(w));
    return d;
}
__device__ __forceinline__ ull pack2(float a, float b) {
    ull d;
    asm("mov.b64 %0, {%1, %2};" : "=l"(d) : "f"(a), "f"(b));
    return d;
}
__device__ __forceinline__ void unpack2(ull v, float& a, float& b) {
    asm("mov.b64 {%0, %1}, %2;" : "=f"(a), "=f"(b) : "l"(v));
}
__device__ __forceinline__ float sigf(float x) {
    float e = __expf(-x);
    return __fdividef(1.0f, 1.0f + e);
}
__device__ __forceinline__ float tanh_fast(float x) {
    float e = __expf(-2.0f * x);
    return __fdividef(1.0f - e, 1.0f + e);
}

// ---------------- prep kernel 1: weight transpose + float4 pack ----------------
__global__ void transpose_weights(
    const float* __restrict__ eWih, const float* __restrict__ eWhh,
    const float* __restrict__ dWih, const float* __restrict__ dWhh)
{
    int idx = blockIdx.x * 256 + threadIdx.x;   // 0 .. 8*16384-1
    int mat = idx >> 14;
    int rem = idx & 16383;
    int k2  = rem >> 8;
    int q   = rem & 255;
    int gp  = q >> 7;
    int tid = q & 127;
    int grp = mat >> 1;
    int lay = mat & 1;
    const float* src =
        (grp == 0 ? eWih : grp == 1 ? eWhh : grp == 2 ? dWih : dWhh) + lay * 65536;
    int r0 = gp * 256 + tid;
    int r1 = r0 + 128;
    g_W4[mat][k2 * 256 + gp * 128 + tid] = make_float4(
        src[r0 * 128 + 2 * k2], src[r0 * 128 + 2 * k2 + 1],
        src[r1 * 128 + 2 * k2], src[r1 * 128 + 2 * k2 + 1]);
}

// ---------------- prep kernel 2: rank-2 folding + bias combine ----------------
__global__ void prep_rank2(
    const float* __restrict__ eWih, const float* __restrict__ dWih,
    const float* __restrict__ emb_W, const float* __restrict__ emb_b,
    const float* __restrict__ enc_bih, const float* __restrict__ enc_bhh,
    const float* __restrict__ dec_bih, const float* __restrict__ dec_bhh)
{
    int idx = blockIdx.x * 256 + threadIdx.x;   // 0..1023
    int mat = idx >> 9;                          // 0 enc, 1 dec
    int row = idx & 511;
    const float* W = (mat ? dWih : eWih) + row * 128;   // layer 0
    float a0 = 0.0f, a1 = 0.0f, ab = 0.0f;
    for (int k = 0; k < 128; ++k) {
        float w = W[k];
        a0 += w * emb_W[2 * k];
        a1 += w * emb_W[2 * k + 1];
        ab += w * emb_b[k];
    }
    const float* bi = mat ? dec_bih : enc_bih;
    const float* bh = mat ? dec_bhh : enc_bhh;
    g_U[mat][0][row] = a0;
    g_U[mat][1][row] = a1;
    g_U[mat][2][row] = ab + bi[row] + bh[row];
    g_B1[mat][row] = bi[512 + row] + bh[512 + row];
    if (mat == 1) g_BD0[row] = bi[row] + bh[row];
}

// ---------------- gate GEMM on batch-row pairs ----------------
__device__ __forceinline__ void gemm_pairs(
    ull (&acc)[NPAIR][4],
    const float2* __restrict__ xb,      // shared, k-major [128][XSTRIDE]
    const float4* __restrict__ W4,      // global, [64][2][128]
    int tid)
{
#pragma unroll 4
    for (int k2 = 0; k2 < 64; ++k2) {
        float4 wa = __ldg(&W4[k2 * 256 + tid]);         // gates i,f
        float4 wb = __ldg(&W4[k2 * 256 + 128 + tid]);   // gates g,o

        const ulonglong2* x0 = (const ulonglong2*)(xb + (2 * k2)     * XSTRIDE);
        const ulonglong2* x1 = (const ulonglong2*)(xb + (2 * k2 + 1) * XSTRIDE);
        ulonglong2 xaL = x0[0], xaH = x0[1];
        ulonglong2 xcL = x1[0], xcH = x1[1];
        ull xa[NPAIR] = { xaL.x, xaL.y, xaH.x, xaH.y };
        ull xc[NPAIR] = { xcL.x, xcL.y, xcH.x, xcH.y };

        // k-even contributions
        {
            ull a0 = dup2(wa.x), a1 = dup2(wa.z);
            ull a2 = dup2(wb.x), a3 = dup2(wb.z);
#pragma unroll
            for (int p = 0; p < NPAIR; ++p) {
                acc[p][0] = ffma2(a0, xa[p], acc[p][0]);
                acc[p][1] = ffma2(a1, xa[p], acc[p][1]);
                acc[p][2] = ffma2(a2, xa[p], acc[p][2]);
                acc[p][3] = ffma2(a3, xa[p], acc[p][3]);
            }
        }
        // k-odd contributions
        {
            ull b0 = dup2(wa.y), b1 = dup2(wa.w);
            ull b2 = dup2(wb.y), b3 = dup2(wb.w);
#pragma unroll
            for (int p = 0; p < NPAIR; ++p) {
                acc[p][0] = ffma2(b0, xc[p], acc[p][0]);
                acc[p][1] = ffma2(b1, xc[p], acc[p][1]);
                acc[p][2] = ffma2(b2, xc[p], acc[p][2]);
                acc[p][3] = ffma2(b3, xc[p], acc[p][3]);
            }
        }
    }
}

// Gate nonlinearity + state update into the NEXT buffer (double-buffered):
// no pre-barrier needed; single post-write barrier publishes the new h.
__device__ __forceinline__ void gate_update(
    ull (&acc)[NPAIR][4],
    float2* __restrict__ hnew,
    float (&cst)[MROWS],
    int tid)
{
#pragma unroll
    for (int p = 0; p < NPAIR; ++p) {
        float i0, i1, f0, f1, g0, g1, o0, o1;
        unpack2(acc[p][0], i0, i1);
        unpack2(acc[p][1], f0, f1);
        unpack2(acc[p][2], g0, g1);
        unpack2(acc[p][3], o0, o1);
        float c0 = sigf(f0) * cst[2 * p]     + sigf(i0) * tanh_fast(g0);
        float c1 = sigf(f1) * cst[2 * p + 1] + sigf(i1) * tanh_fast(g1);
        cst[2 * p]     = c0;
        cst[2 * p + 1] = c1;
        float h0 = sigf(o0) * tanh_fast(c0);
        float h1 = sigf(o1) * tanh_fast(c1);
        *(ull*)(hnew + tid * XSTRIDE + p) = pack2(h0, h1);
    }
    __syncthreads();
}

__global__ __launch_bounds__(NTHREAD, 4)
void lstm_persistent_kernel(
    const float* __restrict__ history,   // (B, 60, 2)
    const float* __restrict__ out_W,     // (2, 128)
    const float* __restrict__ out_b,     // (2)
    float* __restrict__ out)             // (B, 360, 2)
{
    __shared__ __align__(16) float2 hp0[2][HDIM * XSTRIDE];
    __shared__ __align__(16) float2 hp1[2][HDIM * XSTRIDE];
    __shared__ float  hist_sh[T_HIST * MROWS * 2];   // [t][row][d]
    __shared__ float  pred_sh[MROWS][2];
    __shared__ float  outw_sh[2][HDIM];
    __shared__ float  outb_sh[2];

    const int tid = threadIdx.x;
    const int b0  = blockIdx.x * MROWS;

    outw_sh[0][tid] = out_W[tid];
    outw_sh[1][tid] = out_W[128 + tid];
    if (tid < 2) outb_sh[tid] = out_b[tid];

    // Preload this block's history window (coalesced)
    for (int g = tid; g < T_HIST * MROWS * 2; g += NTHREAD) {
        int row = g / (T_HIST * 2);
        int r   = g - row * (T_HIST * 2);    // t*2 + d
        hist_sh[(r >> 1) * (MROWS * 2) + row * 2 + (r & 1)] =
            history[(size_t)(b0 + row) * (T_HIST * 2) + r];
    }

    float cst0[MROWS], cst1[MROWS];
#pragma unroll
    for (int m = 0; m < MROWS; ++m) { cst0[m] = 0.0f; cst1[m] = 0.0f; }
#pragma unroll
    for (int p = 0; p < NPAIR; ++p) {
        hp0[0][tid * XSTRIDE + p] = make_float2(0.0f, 0.0f);
        hp1[0][tid * XSTRIDE + p] = make_float2(0.0f, 0.0f);
    }
    __syncthreads();

    const float4* eU0 = g_W4[2];   // enc layer0 Whh
    const float4* eW1 = g_W4[1];   // enc layer1 Wih
    const float4* eU1 = g_W4[3];   // enc layer1 Whh
    const float4* dU0 = g_W4[6];   // dec layer0 Whh
    const float4* dW1 = g_W4[5];   // dec layer1 Wih
    const float4* dU1 = g_W4[7];   // dec layer1 Whh

    ull acc[NPAIR][4];
    int cur = 0;

    // ---------------- Encoder: 60 steps ----------------
    for (int t = 0; t < T_HIST; ++t) {
        int nxt = cur ^ 1;
        // Layer 0: rank-2 input term + Whh GEMM
        {
            const float* hs = hist_sh + t * (MROWS * 2);
            ull pp0[NPAIR], pp1[NPAIR];
#pragma unroll
            for (int p = 0; p < NPAIR; ++p) {
                pp0[p] = pack2(hs[4 * p],     hs[4 * p + 2]);
                pp1[p] = pack2(hs[4 * p + 1], hs[4 * p + 3]);
            }
#pragma unroll
            for (int j = 0; j < 4; ++j) {
                int g = tid + 128 * j;
                ull a0 = dup2(g_U[0][0][g]);
                ull a1 = dup2(g_U[0][1][g]);
                ull ab = dup2(g_U[0][2][g]);
#pragma unroll
                for (int p = 0; p < NPAIR; ++p)
                    acc[p][j] = ffma2(a0, pp0[p], ffma2(a1, pp1[p], ab));
            }
        }
        gemm_pairs(acc, hp0[cur], eU0, tid);
        gate_update(acc, hp0[nxt], cst0, tid);

        // Layer 1
#pragma unroll
        for (int j = 0; j < 4; ++j) {
            ull b = dup2(g_B1[0][tid + 128 * j]);
#pragma unroll
            for (int p = 0; p < NPAIR; ++p) acc[p][j] = b;
        }
        gemm_pairs(acc, hp0[nxt], eW1, tid);
        gemm_pairs(acc, hp1[cur], eU1, tid);
        gate_update(acc, hp1[nxt], cst1, tid);

        cur = nxt;
    }

    // ---------------- Decoder: 360 autoregressive steps ----------------
    const int wrp  = tid >> 5;
    const int lane = tid & 31;

    for (int t = 0; t < T_OUT; ++t) {
        int nxt = cur ^ 1;
        // Layer 0: rank-2 input term (pred feedback) + Whh GEMM
        if (t == 0) {
#pragma unroll
            for (int j = 0; j < 4; ++j) {
                ull b = dup2(g_BD0[tid + 128 * j]);
#pragma unroll
                for (int p = 0; p < NPAIR; ++p) acc[p][j] = b;
            }
        } else {
            ull pp0[NPAIR], pp1[NPAIR];
#pragma unroll
            for (int p = 0; p < NPAIR; ++p) {
                pp0[p] = pack2(pred_sh[2 * p][0], pred_sh[2 * p + 1][0]);
                pp1[p] = pack2(pred_sh[2 * p][1], pred_sh[2 * p + 1][1]);
            }
#pragma unroll
            for (int j = 0; j < 4; ++j) {
                int g = tid + 128 * j;
                ull a0 = dup2(g_U[1][0][g]);
                ull a1 = dup2(g_U[1][1][g]);
                ull ab = dup2(g_U[1][2][g]);
#pragma unroll
                for (int p = 0; p < NPAIR; ++p)
                    acc[p][j] = ffma2(a0, pp0[p], ffma2(a1, pp1[p], ab));
            }
        }
        gemm_pairs(acc, hp0[cur], dU0, tid);
        gate_update(acc, hp0[nxt], cst0, tid);

        // Layer 1
#pragma unroll
        for (int j = 0; j < 4; ++j) {
            ull b = dup2(g_B1[1][tid + 128 * j]);
#pragma unroll
            for (int p = 0; p < NPAIR; ++p) acc[p][j] = b;
        }
        gemm_pairs(acc, hp0[nxt], dW1, tid);
        gemm_pairs(acc, hp1[cur], dU1, tid);
        gate_update(acc, hp1[nxt], cst1, tid);

        // pred = h1 @ out_W.T + out_b ; warp w handles pair p=w
        {
            int p = wrp;
            float a00 = 0.0f, a01 = 0.0f, a10 = 0.0f, a11 = 0.0f;
#pragma unroll
            for (int j = 0; j < 4; ++j) {
                int k = lane + 32 * j;
                float2 hv = hp1[nxt][k * XSTRIDE + p];
                float w0 = outw_sh[0][k];
                float w1 = outw_sh[1][k];
                a00 += hv.x * w0;  a01 += hv.x * w1;
                a10 += hv.y * w0;  a11 += hv.y * w1;
            }
#pragma unroll
            for (int off = 16; off > 0; off >>= 1) {
                a00 += __shfl_xor_sync(0xffffffffu, a00, off);
                a01 += __shfl_xor_sync(0xffffffffu, a01, off);
                a10 += __shfl_xor_sync(0xffffffffu, a10, off);
                a11 += __shfl_xor_sync(0xffffffffu, a11, off);
            }
            if (lane == 0) {
                float p00 = a00 + outb_sh[0];
                float p01 = a01 + outb_sh[1];
                float p10 = a10 + outb_sh[0];
                float p11 = a11 + outb_sh[1];
                int m0 = 2 * p, m1 = 2 * p + 1;
                pred_sh[m0][0] = p00;  pred_sh[m0][1] = p01;
                pred_sh[m1][0] = p10;  pred_sh[m1][1] = p11;
                size_t o0 = (size_t)(b0 + m0) * (T_OUT * 2) + (size_t)t * 2;
                size_t o1 = (size_t)(b0 + m1) * (T_OUT * 2) + (size_t)t * 2;
                out[o0] = p00;  out[o0 + 1] = p01;
                out[o1] = p10;  out[o1 + 1] = p11;
            }
        }
        __syncthreads();   // pred_sh stable for next step

        cur = nxt;
    }
}

extern "C" void kernel_launch(void* const* d_in, const int* in_sizes, int n_in,
                              void* d_out, int out_size)
{
    const float* history = (const float*)d_in[0];
    const float* emb_W   = (const float*)d_in[1];
    const float* emb_b   = (const float*)d_in[2];
    const float* enc_Wih = (const float*)d_in[3];
    const float* enc_Whh = (const float*)d_in[4];
    const float* enc_bih = (const float*)d_in[5];
    const float* enc_bhh = (const float*)d_in[6];
    const float* dec_Wih = (const float*)d_in[7];
    const float* dec_Whh = (const float*)d_in[8];
    const float* dec_bih = (const float*)d_in[9];
    const float* dec_bhh = (const float*)d_in[10];
    const float* out_W   = (const float*)d_in[11];
    const float* out_b   = (const float*)d_in[12];
    float* out = (float*)d_out;

    transpose_weights<<<512, 256>>>(enc_Wih, enc_Whh, dec_Wih, dec_Whh);
    prep_rank2<<<4, 256>>>(enc_Wih, dec_Wih, emb_W, emb_b,
                           enc_bih, enc_bhh, dec_bih, dec_bhh);

    const int B = 4096;
    lstm_persistent_kernel<<<B / MROWS, NTHREAD>>>(
        history, out_W, out_b, out);
}

// round 16
// speedup vs baseline: 1.6288x; 1.0007x over previous
#include <cuda_runtime.h>
#include <math.h>

// SimpleLSTM: B=4096, T_HIST=60, D_IN=2, H=128, L=2, T_OUT=360
// Persistent kernel, MROWS=8 rows/block, grid=512, 4 CTAs/SM.
// Rank-2 embedding fold; float4-packed k-major weights (2x LDG.128/k2);
// vectorized x loads (LDS.128); double-buffered h states (fewer barriers);
// packed fma.rn.f32x2; MUFU fast sigmoid/tanh.

#define MROWS   8
#define NPAIR   4          // MROWS/2
#define HDIM    128
#define NTHREAD 128
#define T_HIST  60
#define T_OUT   360
#define XSTRIDE 6          // padded row stride (float2), 48B (16B-aligned rows)

typedef unsigned long long ull;

// Packed transposed weights: mats 0:eWih0 1:eWih1 2:eWhh0 3:eWhh1 4:dWih0
// 5:dWih1 6:dWhh0 7:dWhh1. Layout [mat][k2*256 + gp*128 + tid] float4 =
// (W[r0][2k2], W[r0][2k2+1], W[r1][2k2], W[r1][2k2+1]), r0=gp*256+tid, r1=r0+128.
__device__ float4 g_W4[8][64 * 256];
// Rank-2 folded layer-0 input terms: [enc/dec][u0,u1,ub+bias][512 gate rows]
__device__ float  g_U[2][3][512];
// Combined layer-1 biases [enc/dec][512]; decoder layer-0 plain bias [512]
__device__ float  g_B1[2][512];
__device__ float  g_BD0[512];

__device__ __forceinline__ ull ffma2(ull a, ull b, ull c) {
    ull d;
    asm("fma.rn.f32x2 %0, %1, %2, %3;" : "=l"(d) : "l"(a), "l"(b), "l"(c));
    return d;
}
__device__ __forceinline__ ull dup2(float w) {
    ull d;
    asm("mov.b64 %0, {%1, %1};" : "=l"(d) : "f"(w));
    return d;
}
__device__ __forceinline__ ull pack2(float a, float b) {
    ull d;
    asm("mov.b64 %0, {%1, %2};" : "=l"(d) : "f"(a), "f"(b));
    return d;
}
__device__ __forceinline__ void unpack2(ull v, float& a, float& b) {
    asm("mov.b64 {%0, %1}, %2;" : "=f"(a), "=f"(b) : "l"(v));
}
__device__ __forceinline__ float sigf(float x) {
    float e = __expf(-x);
    return __fdividef(1.0f, 1.0f + e);
}
__device__ __forceinline__ float tanh_fast(float x) {
    float e = __expf(-2.0f * x);
    return __fdividef(1.0f - e, 1.0f + e);
}

// ---------------- prep kernel 1: weight transpose + float4 pack ----------------
__global__ void transpose_weights(
    const float* __restrict__ eWih, const float* __restrict__ eWhh,
    const float* __restrict__ dWih, const float* __restrict__ dWhh)
{
    int idx = blockIdx.x * 256 + threadIdx.x;   // 0 .. 8*16384-1
    int mat = idx >> 14;
    int rem = idx & 16383;
    int k2  = rem >> 8;
    int q   = rem & 255;
    int gp  = q >> 7;
    int tid = q & 127;
    int grp = mat >> 1;
    int lay = mat & 1;
    const float* src =
        (grp == 0 ? eWih : grp == 1 ? eWhh : grp == 2 ? dWih : dWhh) + lay * 65536;
    int r0 = gp * 256 + tid;
    int r1 = r0 + 128;
    g_W4[mat][k2 * 256 + gp * 128 + tid] = make_float4(
        src[r0 * 128 + 2 * k2], src[r0 * 128 + 2 * k2 + 1],
        src[r1 * 128 + 2 * k2], src[r1 * 128 + 2 * k2 + 1]);
}

// ---------------- prep kernel 2: rank-2 folding + bias combine ----------------
__global__ void prep_rank2(
    const float* __restrict__ eWih, const float* __restrict__ dWih,
    const float* __restrict__ emb_W, const float* __restrict__ emb_b,
    const float* __restrict__ enc_bih, const float* __restrict__ enc_bhh,
    const float* __restrict__ dec_bih, const float* __restrict__ dec_bhh)
{
    int idx = blockIdx.x * 256 + threadIdx.x;   // 0..1023
    int mat = idx >> 9;                          // 0 enc, 1 dec
    int row = idx & 511;
    const float* W = (mat ? dWih : eWih) + row * 128;   // layer 0
    float a0 = 0.0f, a1 = 0.0f, ab = 0.0f;
    for (int k = 0; k < 128; ++k) {
        float w = W[k];
        a0 += w * emb_W[2 * k];
        a1 += w * emb_W[2 * k + 1];
        ab += w * emb_b[k];
    }
    const float* bi = mat ? dec_bih : enc_bih;
    const float* bh = mat ? dec_bhh : enc_bhh;
    g_U[mat][0][row] = a0;
    g_U[mat][1][row] = a1;
    g_U[mat][2][row] = ab + bi[row] + bh[row];
    g_B1[mat][row] = bi[512 + row] + bh[512 + row];
    if (mat == 1) g_BD0[row] = bi[row] + bh[row];
}

// ---------------- gate GEMM on batch-row pairs ----------------
__device__ __forceinline__ void gemm_pairs(
    ull (&acc)[NPAIR][4],
    const float2* __restrict__ xb,      // shared, k-major [128][XSTRIDE]
    const float4* __restrict__ W4,      // global, [64][2][128]
    int tid)
{
#pragma unroll 4
    for (int k2 = 0; k2 < 64; ++k2) {
        float4 wa = __ldg(&W4[k2 * 256 + tid]);         // gates i,f
        float4 wb = __ldg(&W4[k2 * 256 + 128 + tid]);   // gates g,o

        const ulonglong2* x0 = (const ulonglong2*)(xb + (2 * k2)     * XSTRIDE);
        const ulonglong2* x1 = (const ulonglong2*)(xb + (2 * k2 + 1) * XSTRIDE);
        ulonglong2 xaL = x0[0], xaH = x0[1];
        ulonglong2 xcL = x1[0], xcH = x1[1];
        ull xa[NPAIR] = { xaL.x, xaL.y, xaH.x, xaH.y };
        ull xc[NPAIR] = { xcL.x, xcL.y, xcH.x, xcH.y };

        // k-even contributions
        {
            ull a0 = dup2(wa.x), a1 = dup2(wa.z);
            ull a2 = dup2(wb.x), a3 = dup2(wb.z);
#pragma unroll
            for (int p = 0; p < NPAIR; ++p) {
                acc[p][0] = ffma2(a0, xa[p], acc[p][0]);
                acc[p][1] = ffma2(a1, xa[p], acc[p][1]);
                acc[p][2] = ffma2(a2, xa[p], acc[p][2]);
                acc[p][3] = ffma2(a3, xa[p], acc[p][3]);
            }
        }
        // k-odd contributions
        {
            ull b0 = dup2(wa.y), b1 = dup2(wa.w);
            ull b2 = dup2(wb.y), b3 = dup2(wb.w);
#pragma unroll
            for (int p = 0; p < NPAIR; ++p) {
                acc[p][0] = ffma2(b0, xc[p], acc[p][0]);
                acc[p][1] = ffma2(b1, xc[p], acc[p][1]);
                acc[p][2] = ffma2(b2, xc[p], acc[p][2]);
                acc[p][3] = ffma2(b3, xc[p], acc[p][3]);
            }
        }
    }
}

// Gate nonlinearity + state update into the NEXT buffer (double-buffered):
// no pre-barrier needed; single post-write barrier publishes the new h.
__device__ __forceinline__ void gate_update(
    ull (&acc)[NPAIR][4],
    float2* __restrict__ hnew,
    float (&cst)[MROWS],
    int tid)
{
#pragma unroll
    for (int p = 0; p < NPAIR; ++p) {
        float i0, i1, f0, f1, g0, g1, o0, o1;
        unpack2(acc[p][0], i0, i1);
        unpack2(acc[p][1], f0, f1);
        unpack2(acc[p][2], g0, g1);
        unpack2(acc[p][3], o0, o1);
        float c0 = sigf(f0) * cst[2 * p]     + sigf(i0) * tanh_fast(g0);
        float c1 = sigf(f1) * cst[2 * p + 1] + sigf(i1) * tanh_fast(g1);
        cst[2 * p]     = c0;
        cst[2 * p + 1] = c1;
        float h0 = sigf(o0) * tanh_fast(c0);
        float h1 = sigf(o1) * tanh_fast(c1);
        *(ull*)(hnew + tid * XSTRIDE + p) = pack2(h0, h1);
    }
    __syncthreads();
}

__global__ __launch_bounds__(NTHREAD, 4)
void lstm_persistent_kernel(
    const float* __restrict__ history,   // (B, 60, 2)
    const float* __restrict__ out_W,     // (2, 128)
    const float* __restrict__ out_b,     // (2)
    float* __restrict__ out)             // (B, 360, 2)
{
    __shared__ __align__(16) float2 hp0[2][HDIM * XSTRIDE];
    __shared__ __align__(16) float2 hp1[2][HDIM * XSTRIDE];
    __shared__ float  hist_sh[T_HIST * MROWS * 2];   // [t][row][d]
    __shared__ float  pred_sh[MROWS][2];
    __shared__ float  outw_sh[2][HDIM];
    __shared__ float  outb_sh[2];

    const int tid = threadIdx.x;
    const int b0  = blockIdx.x * MROWS;

    outw_sh[0][tid] = out_W[tid];
    outw_sh[1][tid] = out_W[128 + tid];
    if (tid < 2) outb_sh[tid] = out_b[tid];

    // Preload this block's history window (coalesced)
    for (int g = tid; g < T_HIST * MROWS * 2; g += NTHREAD) {
        int row = g / (T_HIST * 2);
        int r   = g - row * (T_HIST * 2);    // t*2 + d
        hist_sh[(r >> 1) * (MROWS * 2) + row * 2 + (r & 1)] =
            history[(size_t)(b0 + row) * (T_HIST * 2) + r];
    }

    float cst0[MROWS], cst1[MROWS];
#pragma unroll
    for (int m = 0; m < MROWS; ++m) { cst0[m] = 0.0f; cst1[m] = 0.0f; }
#pragma unroll
    for (int p = 0; p < NPAIR; ++p) {
        hp0[0][tid * XSTRIDE + p] = make_float2(0.0f, 0.0f);
        hp1[0][tid * XSTRIDE + p] = make_float2(0.0f, 0.0f);
    }
    __syncthreads();

    const float4* eU0 = g_W4[2];   // enc layer0 Whh
    const float4* eW1 = g_W4[1];   // enc layer1 Wih
    const float4* eU1 = g_W4[3];   // enc layer1 Whh
    const float4* dU0 = g_W4[6];   // dec layer0 Whh
    const float4* dW1 = g_W4[5];   // dec layer1 Wih
    const float4* dU1 = g_W4[7];   // dec layer1 Whh

    ull acc[NPAIR][4];
    int cur = 0;

    // ---------------- Encoder: 60 steps ----------------
    for (int t = 0; t < T_HIST; ++t) {
        int nxt = cur ^ 1;
        // Layer 0: rank-2 input term + Whh GEMM
        {
            const float* hs = hist_sh + t * (MROWS * 2);
            ull pp0[NPAIR], pp1[NPAIR];
#pragma unroll
            for (int p = 0; p < NPAIR; ++p) {
                pp0[p] = pack2(hs[4 * p],     hs[4 * p + 2]);
                pp1[p] = pack2(hs[4 * p + 1], hs[4 * p + 3]);
            }
#pragma unroll
            for (int j = 0; j < 4; ++j) {
                int g = tid + 128 * j;
                ull a0 = dup2(g_U[0][0][g]);
                ull a1 = dup2(g_U[0][1][g]);
                ull ab = dup2(g_U[0][2][g]);
#pragma unroll
                for (int p = 0; p < NPAIR; ++p)
                    acc[p][j] = ffma2(a0, pp0[p], ffma2(a1, pp1[p], ab));
            }
        }
        gemm_pairs(acc, hp0[cur], eU0, tid);
        gate_update(acc, hp0[nxt], cst0, tid);

        // Layer 1
#pragma unroll
        for (int j = 0; j < 4; ++j) {
            ull b = dup2(g_B1[0][tid + 128 * j]);
#pragma unroll
            for (int p = 0; p < NPAIR; ++p) acc[p][j] = b;
        }
        gemm_pairs(acc, hp0[nxt], eW1, tid);
        gemm_pairs(acc, hp1[cur], eU1, tid);
        gate_update(acc, hp1[nxt], cst1, tid);

        cur = nxt;
    }

    // ---------------- Decoder: 360 autoregressive steps ----------------
    const int wrp  = tid >> 5;
    const int lane = tid & 31;

    for (int t = 0; t < T_OUT; ++t) {
        int nxt = cur ^ 1;
        // Layer 0: rank-2 input term (pred feedback) + Whh GEMM
        if (t == 0) {
#pragma unroll
            for (int j = 0; j < 4; ++j) {
                ull b = dup2(g_BD0[tid + 128 * j]);
#pragma unroll
                for (int p = 0; p < NPAIR; ++p) acc[p][j] = b;
            }
        } else {
            ull pp0[NPAIR], pp1[NPAIR];
#pragma unroll
            for (int p = 0; p < NPAIR; ++p) {
                pp0[p] = pack2(pred_sh[2 * p][0], pred_sh[2 * p + 1][0]);
                pp1[p] = pack2(pred_sh[2 * p][1], pred_sh[2 * p + 1][1]);
            }
#pragma unroll
            for (int j = 0; j < 4; ++j) {
                int g = tid + 128 * j;
                ull a0 = dup2(g_U[1][0][g]);
                ull a1 = dup2(g_U[1][1][g]);
                ull ab = dup2(g_U[1][2][g]);
#pragma unroll
                for (int p = 0; p < NPAIR; ++p)
                    acc[p][j] = ffma2(a0, pp0[p], ffma2(a1, pp1[p], ab));
            }
        }
        gemm_pairs(acc, hp0[cur], dU0, tid);
        gate_update(acc, hp0[nxt], cst0, tid);

        // Layer 1
#pragma unroll
        for (int j = 0; j < 4; ++j) {
            ull b = dup2(g_B1[1][tid + 128 * j]);
#pragma unroll
            for (int p = 0; p < NPAIR; ++p) acc[p][j] = b;
        }
        gemm_pairs(acc, hp0[nxt], dW1, tid);
        gemm_pairs(acc, hp1[cur], dU1, tid);
        gate_update(acc, hp1[nxt], cst1, tid);

        // pred = h1 @ out_W.T + out_b ; warp w handles pair p=w
        {
            int p = wrp;
            float a00 = 0.0f, a01 = 0.0f, a10 = 0.0f, a11 = 0.0f;
#pragma unroll
            for (int j = 0; j < 4; ++j) {
                int k = lane + 32 * j;
                float2 hv = hp1[nxt][k * XSTRIDE + p];
                float w0 = outw_sh[0][k];
                float w1 = outw_sh[1][k];
                a00 += hv.x * w0;  a01 += hv.x * w1;
                a10 += hv.y * w0;  a11 += hv.y * w1;
            }
#pragma unroll
            for (int off = 16; off > 0; off >>= 1) {
                a00 += __shfl_xor_sync(0xffffffffu, a00, off);
                a01 += __shfl_xor_sync(0xffffffffu, a01, off);
                a10 += __shfl_xor_sync(0xffffffffu, a10, off);
                a11 += __shfl_xor_sync(0xffffffffu, a11, off);
            }
            if (lane == 0) {
                float p00 = a00 + outb_sh[0];
                float p01 = a01 + outb_sh[1];
                float p10 = a10 + outb_sh[0];
                float p11 = a11 + outb_sh[1];
                int m0 = 2 * p, m1 = 2 * p + 1;
                pred_sh[m0][0] = p00;  pred_sh[m0][1] = p01;
                pred_sh[m1][0] = p10;  pred_sh[m1][1] = p11;
                size_t o0 = (size_t)(b0 + m0) * (T_OUT * 2) + (size_t)t * 2;
                size_t o1 = (size_t)(b0 + m1) * (T_OUT * 2) + (size_t)t * 2;
                out[o0] = p00;  out[o0 + 1] = p01;
                out[o1] = p10;  out[o1 + 1] = p11;
            }
        }
        __syncthreads();   // pred_sh stable for next step

        cur = nxt;
    }
}

extern "C" void kernel_launch(void* const* d_in, const int* in_sizes, int n_in,
                              void* d_out, int out_size)
{
    const float* history = (const float*)d_in[0];
    const float* emb_W   = (const float*)d_in[1];
    const float* emb_b   = (const float*)d_in[2];
    const float* enc_Wih = (const float*)d_in[3];
    const float* enc_Whh = (const float*)d_in[4];
    const float* enc_bih = (const float*)d_in[5];
    const float* enc_bhh = (const float*)d_in[6];
    const float* dec_Wih = (const float*)d_in[7];
    const float* dec_Whh = (const float*)d_in[8];
    const float* dec_bih = (const float*)d_in[9];
    const float* dec_bhh = (const float*)d_in[10];
    const float* out_W   = (const float*)d_in[11];
    const float* out_b   = (const float*)d_in[12];
    float* out = (float*)d_out;

    transpose_weights<<<512, 256>>>(enc_Wih, enc_Whh, dec_Wih, dec_Whh);
    prep_rank2<<<4, 256>>>(enc_Wih, dec_Wih, emb_W, emb_b,
                           enc_bih, enc_bhh, dec_bih, dec_bhh);

    const int B = 4096;
    lstm_persistent_kernel<<<B / MROWS, NTHREAD>>>(
        history, out_W, out_b, out);
}